// round 13
// baseline (speedup 1.0000x reference)
#include <cuda_runtime.h>
#include <cuda_fp16.h>
#include <mma.h>
#include <cstdint>
#include <cstddef>

using namespace nvcuda;

// ---------------------------------------------------------------------------
// MegNetBlock — persistent wmma fp16 single-pass, ping-pong bufs,
// register-resident ue/uv readout.  N=100000, E=800000, D=64, H=128
// ---------------------------------------------------------------------------

#define NMAX 100000
typedef unsigned int u32;

// ---------------- scratch (device globals) ----------------
__device__ float  g_v_pre[NMAX * 64];
__device__ float4 g_As[NMAX * 32];
__device__ float4 g_Ad[NMAX * 32];
__device__ float  g_ve[NMAX * 64];
__device__ float  g_cnt[NMAX];
__device__ float  g_u_pre[64];
__device__ __align__(16) float g_ce[128];
__device__ __align__(16) float g_cn[128];
__device__ float  g_ue[64];
__device__ float  g_uv[64];

// fp16 weights, [k][n] row-major per segment (offsets in elems)
//  0 Wp 0 (64x64) | 1 W0e 4096 (64x128) | 2 W1e 12288 (128x128)
//  3 W2e 28672 (128x64) | 4 W0n 36864 | 5 W1n 53248 | 6 W2n 69632
__device__ __align__(16) __half g_W[77824];

// ---------------- smem layouts (byte offsets) ----------------
static constexpr int SA = 136;   // A row stride in fp16 elems

// edge kernel (512 threads, 16 warps, 128 rows/iter)
static constexpr int E_WP  = 0;        // 64x72   = 9216
static constexpr int E_W0  = 9216;     // 64x136  = 17408
static constexpr int E_W1  = 26624;    // 128x136 = 34816
static constexpr int E_W2  = 61440;    // 128x72  = 18432
static constexpr int E_A0  = 79872;    // 128x136 fp16 = 34816
static constexpr int E_A1  = 114688;   // 34816
static constexpr int E_STG = 149504;   // 16 x 16x20 f32 = 20480
static constexpr int E_MISC = 169984;  // src 512|dst 512|pb 256|b1 512|b2 256|ce 512
static constexpr int E_TOTAL = 172544;

// node kernel (512 threads, 128 rows/iter)
static constexpr int N_W0  = 0;        // 34816
static constexpr int N_W1  = 34816;    // 34816
static constexpr int N_W2  = 69632;    // 18432
static constexpr int N_A0  = 88064;    // 34816
static constexpr int N_A1  = 122880;   // 34816
static constexpr int N_STG = 157696;   // 20480
static constexpr int N_MISC = 178176;  // cn 512|b1 512|b2 256
static constexpr int N_TOTAL = 179456;

static constexpr int NUM_CTAS = 148;

// ---------------- helpers ----------------
__device__ __forceinline__ float sp(float x) {
    return fmaxf(x, 0.0f) + __logf(1.0f + __expf(-fabsf(x)));
}
__device__ __forceinline__ u32 pack2h(float a, float b) {
    __half2 h = __floats2half2_rn(a, b);
    return *(u32*)&h;
}

typedef wmma::fragment<wmma::matrix_a, 16, 16, 16, __half, wmma::row_major> FragA;
typedef wmma::fragment<wmma::matrix_b, 16, 16, 16, __half, wmma::row_major> FragB;
typedef wmma::fragment<wmma::accumulator, 16, 16, 16, float> FragC;

__device__ __forceinline__ void mma_half(const char* smem, int offA, int offW,
                                         int row0, int K, int SW, int colbase,
                                         int nt, FragC* acc) {
    const __half* A = (const __half*)(smem + offA) + row0 * SA;
    const __half* W = (const __half*)(smem + offW) + colbase;
    for (int n = 0; n < nt; n++) wmma::fill_fragment(acc[n], 0.0f);
    for (int k = 0; k < K; k += 16) {
        FragA a;
        wmma::load_matrix_sync(a, A + k, SA);
        for (int n = 0; n < nt; n++) {
            FragB b;
            wmma::load_matrix_sync(b, W + k * SW + n * 16, SW);
            wmma::mma_sync(acc[n], a, b, acc[n]);
        }
    }
}

__device__ __forceinline__ void load_W_seg(char* smem, int goff, int K, int N, int SW,
                                           int off, int tid, int nthr) {
    const u32* gw = (const u32*)(g_W + goff);
    int total2 = K * N / 2;
    for (int i2 = tid; i2 < total2; i2 += nthr) {
        int k = (2 * i2) / N, n = (2 * i2) % N;
        *(u32*)(smem + off + (k * SW + n) * 2) = gw[i2];
    }
}

__device__ __forceinline__ void store_A8(char* smem, int offA, int row, int col,
                                         const float* v) {
#pragma unroll
    for (int j = 0; j < 8; j += 2)
        *(u32*)(smem + offA + (row * SA + col + j) * 2) = pack2h(v[j], v[j + 1]);
}

// ---------------------------------------------------------------------------
__global__ void zero_kernel(int nNodes) {
    int total = nNodes * 64 + nNodes + 128;
    for (int i = blockIdx.x * blockDim.x + threadIdx.x; i < total;
         i += gridDim.x * blockDim.x) {
        if (i < nNodes * 64) g_ve[i] = 0.0f;
        else if (i < nNodes * 64 + nNodes) g_cnt[i - nNodes * 64] = 0.0f;
        else {
            int j = i - nNodes * 64 - nNodes;
            if (j < 64) g_ue[j] = 0.0f; else g_uv[j - 64] = 0.0f;
        }
    }
}

__global__ void pre_attr_kernel(const float* __restrict__ ga,
                                const float* __restrict__ w,
                                const float* __restrict__ b) {
    __shared__ float sg[64];
    int t = threadIdx.x;
    sg[t] = ga[t];
    __syncthreads();
    float acc = b[t];
    for (int k = 0; k < 64; k++) acc = fmaf(sg[k], w[k * 64 + t], acc);
    g_u_pre[t] = sp(acc);
}

__global__ void const_kernel(const float* __restrict__ ew0,
                             const float* __restrict__ eb0,
                             const float* __restrict__ nw0,
                             const float* __restrict__ nb0) {
    __shared__ float su[64];
    int t = threadIdx.x;  // 128
    if (t < 64) su[t] = g_u_pre[t];
    __syncthreads();
    float a = eb0[t], c = nb0[t];
    for (int k = 0; k < 64; k++) {
        a = fmaf(su[k], ew0[(192 + k) * 128 + t], a);
        c = fmaf(su[k], nw0[(128 + k) * 128 + t], c);
    }
    g_ce[t] = a;
    g_cn[t] = c;
}

__global__ void prep_w_kernel(const float* pw, const float* ew0,
                              const float* ew1, const float* ew2,
                              const float* nw0, const float* nw1,
                              const float* nw2) {
    const float* srcs[7] = {pw, ew0 + 128 * 128, ew1, ew2, nw0, nw1, nw2};
    const int KN[7] = {4096, 8192, 16384, 8192, 16384, 16384, 8192};
    const int off[7] = {0, 4096, 12288, 28672, 36864, 53248, 69632};
#pragma unroll 1
    for (int s = 0; s < 7; s++) {
        const float* sc = srcs[s];
        for (int i = blockIdx.x * blockDim.x + threadIdx.x; i < KN[s];
             i += gridDim.x * blockDim.x)
            g_W[off[s] + i] = __float2half_rn(sc[i]);
    }
}

// ---------------------------------------------------------------------------
__global__ __launch_bounds__(128) void pre_nodeA_kernel(
    const float* __restrict__ nf, const float* __restrict__ pw,
    const float* __restrict__ pb, const float* __restrict__ ew0) {
    __shared__ float snf[2048];
    __shared__ float sv[2048];
    int tid = threadIdx.x;
    size_t base = (size_t)blockIdx.x * 32;

    for (int i = tid; i < 512; i += 128)
        ((float4*)snf)[i] = ((const float4*)(nf + base * 64))[i];
    __syncthreads();

    {
        int col = tid & 63, hf = tid >> 6;
        float bb = pb[col];
        float acc[16];
#pragma unroll
        for (int i = 0; i < 16; i++) acc[i] = bb;
        const float* xr = snf + hf * 16 * 64;
        for (int k = 0; k < 64; k += 4) {
            float wa = __ldg(pw + k * 64 + col), wb = __ldg(pw + (k + 1) * 64 + col);
            float wc = __ldg(pw + (k + 2) * 64 + col), wd = __ldg(pw + (k + 3) * 64 + col);
#pragma unroll
            for (int i = 0; i < 16; i++) {
                float4 xv = *(const float4*)(xr + i * 64 + k);
                acc[i] = fmaf(xv.x, wa, acc[i]);
                acc[i] = fmaf(xv.y, wb, acc[i]);
                acc[i] = fmaf(xv.z, wc, acc[i]);
                acc[i] = fmaf(xv.w, wd, acc[i]);
            }
        }
#pragma unroll
        for (int i = 0; i < 16; i++) {
            float v = sp(acc[i]);
            sv[(hf * 16 + i) * 64 + col] = v;
            g_v_pre[(base + hf * 16 + i) * 64 + col] = v;
        }
    }
    __syncthreads();

    float* Asf = (float*)g_As;
    float* Adf = (float*)g_Ad;
    int j = tid;
#pragma unroll 1
    for (int m = 0; m < 2; m++) {
        const float* w = ew0 + (size_t)m * 64 * 128;
        float acc[32];
#pragma unroll
        for (int e = 0; e < 32; e++) acc[e] = 0.0f;
        for (int k = 0; k < 64; k += 4) {
            float wa = __ldg(w + k * 128 + j), wb = __ldg(w + (k + 1) * 128 + j);
            float wc = __ldg(w + (k + 2) * 128 + j), wd = __ldg(w + (k + 3) * 128 + j);
#pragma unroll
            for (int e = 0; e < 32; e++) {
                float4 xv = *(const float4*)(sv + e * 64 + k);
                acc[e] = fmaf(xv.x, wa, acc[e]);
                acc[e] = fmaf(xv.y, wb, acc[e]);
                acc[e] = fmaf(xv.z, wc, acc[e]);
                acc[e] = fmaf(xv.w, wd, acc[e]);
            }
        }
        float* dstp = m ? Adf : Asf;
#pragma unroll
        for (int e = 0; e < 32; e++) dstp[(base + e) * 128 + j] = acc[e];
    }
}

// ---------------------------------------------------------------------------
// persistent edge kernel: 128 edges / iteration, 512 threads / 16 warps
// ping-pong: p0 A0->A1, p1 A1->A0, p2 A0->A1, p3 A1->global (+ue_reg)
// 5 syncs/iter
// ---------------------------------------------------------------------------
__global__ __launch_bounds__(512) void edge_kernel(
    const float* __restrict__ ef, const int* __restrict__ srcI,
    const int* __restrict__ dstI, const float* __restrict__ pb,
    const float* __restrict__ b1, const float* __restrict__ b2,
    float* __restrict__ e_out, int nTiles) {
    extern __shared__ char smem[];
    int tid = threadIdx.x, wid = tid >> 5, lane = tid & 31;

    int*   s_src = (int*)(smem + E_MISC);
    int*   s_dst = (int*)(smem + E_MISC + 512);
    float* s_pb  = (float*)(smem + E_MISC + 1024);
    float* s_b1  = (float*)(smem + E_MISC + 1280);
    float* s_b2  = (float*)(smem + E_MISC + 1792);
    float* s_ce  = (float*)(smem + E_MISC + 2048);
    float* stg   = (float*)(smem + E_STG) + wid * 320;

    load_W_seg(smem, 0,     64, 64,  72, E_WP, tid, 512);
    load_W_seg(smem, 4096,  64, 128, 136, E_W0, tid, 512);
    load_W_seg(smem, 12288, 128, 128, 136, E_W1, tid, 512);
    load_W_seg(smem, 28672, 128, 64,  72, E_W2, tid, 512);
    if (tid < 128) {
        s_ce[tid] = g_ce[tid];
        s_b1[tid] = __ldg(b1 + tid);
    } else if (tid < 192) {
        s_pb[tid - 128] = __ldg(pb + tid - 128);
    } else if (tid < 256) {
        s_b2[tid - 192] = __ldg(b2 + tid - 192);
    }

    int slab = wid & 7, h = wid >> 3, row0 = slab * 16;
    int r = lane >> 1, c0 = (lane & 1) * 8, row = row0 + r;
    float ue_reg[16];
#pragma unroll
    for (int i = 0; i < 16; i++) ue_reg[i] = 0.0f;
    FragC acc[4];

    for (int t = blockIdx.x; t < nTiles; t += gridDim.x) {
        size_t base = (size_t)t * 128;
        __syncthreads();  // prev iter fully done (p3 read A1 + s_dst); W visible

        if (tid < 128) {
            s_src[tid] = srcI[base + tid];
            s_dst[tid] = dstI[base + tid];
        }
        // stage ef -> A0: 2048 float4s
        for (int i = tid; i < 2048; i += 512) {
            int rr = i >> 4, q = i & 15;
            float4 v = __ldg((const float4*)(ef + (base + rr) * 64) + q);
            int c = q * 4;
            *(u32*)(smem + E_A0 + (rr * SA + c) * 2) = pack2h(v.x, v.y);
            *(u32*)(smem + E_A0 + (rr * SA + c + 2) * 2) = pack2h(v.z, v.w);
        }
        __syncthreads();

        // ---- phase 0: pre-edge K=64 N=64, A0 -> A1 ----
        mma_half(smem, E_A0, E_WP, row0, 64, 72, h * 32, 2, acc);
#pragma unroll
        for (int n = 0; n < 2; n++) {
            wmma::store_matrix_sync(stg, acc[n], 20, wmma::mem_row_major);
            __syncwarp();
            int col = h * 32 + n * 16 + c0;
            float v[8];
#pragma unroll
            for (int j = 0; j < 8; j++) v[j] = sp(stg[r * 20 + c0 + j] + s_pb[col + j]);
            store_A8(smem, E_A1, row, col, v);
            __syncwarp();
        }
        __syncthreads();

        // ---- phase 1: L0 K=64 N=128 (+As[src]+Ad[dst]+ce), A1 -> A0 ----
        mma_half(smem, E_A1, E_W0, row0, 64, 136, h * 64, 4, acc);
        {
            const float4* as4 = (const float4*)g_As + (size_t)s_src[row] * 32;
            const float4* ad4 = (const float4*)g_Ad + (size_t)s_dst[row] * 32;
#pragma unroll
            for (int n = 0; n < 4; n++) {
                wmma::store_matrix_sync(stg, acc[n], 20, wmma::mem_row_major);
                __syncwarp();
                int col = h * 64 + n * 16 + c0;
                float4 a0 = __ldg(as4 + (col >> 2)), a1 = __ldg(as4 + (col >> 2) + 1);
                float4 d0 = __ldg(ad4 + (col >> 2)), d1 = __ldg(ad4 + (col >> 2) + 1);
                float ga[8] = {a0.x + d0.x, a0.y + d0.y, a0.z + d0.z, a0.w + d0.w,
                               a1.x + d1.x, a1.y + d1.y, a1.z + d1.z, a1.w + d1.w};
                float v[8];
#pragma unroll
                for (int j = 0; j < 8; j++)
                    v[j] = sp(stg[r * 20 + c0 + j] + ga[j] + s_ce[col + j]);
                store_A8(smem, E_A0, row, col, v);
                __syncwarp();
            }
        }
        __syncthreads();

        // ---- phase 2: L1 K=128 N=128, A0 -> A1 ----
        mma_half(smem, E_A0, E_W1, row0, 128, 136, h * 64, 4, acc);
#pragma unroll
        for (int n = 0; n < 4; n++) {
            wmma::store_matrix_sync(stg, acc[n], 20, wmma::mem_row_major);
            __syncwarp();
            int col = h * 64 + n * 16 + c0;
            float v[8];
#pragma unroll
            for (int j = 0; j < 8; j++) v[j] = sp(stg[r * 20 + c0 + j] + s_b1[col + j]);
            store_A8(smem, E_A1, row, col, v);
            __syncwarp();
        }
        __syncthreads();

        // ---- phase 3: L2 K=128 N=64, A1 -> global (+ue_reg) ----
        mma_half(smem, E_A1, E_W2, row0, 128, 72, h * 32, 2, acc);
        {
            int dnode = s_dst[row];
#pragma unroll
            for (int n = 0; n < 2; n++) {
                wmma::store_matrix_sync(stg, acc[n], 20, wmma::mem_row_major);
                __syncwarp();
                int col = h * 32 + n * 16 + c0;
                float v[8];
#pragma unroll
                for (int j = 0; j < 8; j++)
                    v[j] = sp(stg[r * 20 + c0 + j] + s_b2[col + j]);
                size_t gidx = (base + row) * 64 + col;
                float4 e0 = __ldg((const float4*)(ef + gidx));
                float4 e1 = __ldg((const float4*)(ef + gidx) + 1);
                float4 o0 = {v[0] + e0.x, v[1] + e0.y, v[2] + e0.z, v[3] + e0.w};
                float4 o1 = {v[4] + e1.x, v[5] + e1.y, v[6] + e1.z, v[7] + e1.w};
                *(float4*)(e_out + gidx) = o0;
                *((float4*)(e_out + gidx) + 1) = o1;
                float* vrow = &g_ve[(size_t)dnode * 64 + col];
#pragma unroll
                for (int j = 0; j < 8; j++) {
                    atomicAdd(vrow + j, v[j]);
                    ue_reg[n * 8 + j] += v[j];
                }
                if (n == 0 && h == 0 && (lane & 1) == 0)
                    atomicAdd(&g_cnt[dnode], 1.0f);
                __syncwarp();
            }
        }
    }

    // final ue reduction: shfl over the warp's 16 row-lanes, atomic per column
#pragma unroll
    for (int n = 0; n < 2; n++) {
#pragma unroll
        for (int j = 0; j < 8; j++) {
            float s = ue_reg[n * 8 + j];
            s += __shfl_xor_sync(0xFFFFFFFFu, s, 2);
            s += __shfl_xor_sync(0xFFFFFFFFu, s, 4);
            s += __shfl_xor_sync(0xFFFFFFFFu, s, 8);
            s += __shfl_xor_sync(0xFFFFFFFFu, s, 16);
            if ((lane >> 1) == 0)
                atomicAdd(&g_ue[h * 32 + n * 16 + (lane & 1) * 8 + j], s);
        }
    }
}

// ---------------------------------------------------------------------------
// persistent node kernel: 128 nodes / iteration, 512 threads
// ping-pong: L0 A0->A1, L1 A1->A0, L2 A0 -> global (+uv_reg); 4 syncs/iter
// ---------------------------------------------------------------------------
__global__ __launch_bounds__(512) void node_kernel(
    const float* __restrict__ nf, const float* __restrict__ b1,
    const float* __restrict__ b2, float* __restrict__ v_out, int nNodes,
    int nTiles) {
    extern __shared__ char smem[];
    int tid = threadIdx.x, wid = tid >> 5, lane = tid & 31;

    float* s_cn  = (float*)(smem + N_MISC);
    float* s_b1  = (float*)(smem + N_MISC + 512);
    float* s_b2  = (float*)(smem + N_MISC + 1024);
    float* stg   = (float*)(smem + N_STG) + wid * 320;

    load_W_seg(smem, 36864, 128, 128, 136, N_W0, tid, 512);
    load_W_seg(smem, 53248, 128, 128, 136, N_W1, tid, 512);
    load_W_seg(smem, 69632, 128, 64,  72, N_W2, tid, 512);
    if (tid < 128) {
        s_cn[tid] = g_cn[tid];
        s_b1[tid] = __ldg(b1 + tid);
    } else if (tid < 192) {
        s_b2[tid - 128] = (tid - 128 < 64) ? __ldg(b2 + tid - 128) : 0.0f;
    }

    int slab = wid & 7, h = wid >> 3, row0 = slab * 16;
    int r = lane >> 1, c0 = (lane & 1) * 8, row = row0 + r;
    float uv_reg[16];
#pragma unroll
    for (int i = 0; i < 16; i++) uv_reg[i] = 0.0f;
    FragC acc[4];

    for (int t = blockIdx.x; t < nTiles; t += gridDim.x) {
        size_t base = (size_t)t * 128;
        __syncthreads();  // prev L2 (read A0) done

        // stage X = [v_pre | ve_mean] (K=128) -> A0
        {
            int rr = tid & 127, hh = tid >> 7;  // hh 0..3
            size_t gn = base + rr;
            if (gn >= (size_t)nNodes) gn = nNodes - 1;
            const float4* g4;
            float scale = 1.0f;
            if (hh < 2) {
                g4 = (const float4*)(g_v_pre + gn * 64) + hh * 8;
            } else {
                g4 = (const float4*)(g_ve + gn * 64) + (hh - 2) * 8;
                scale = 1.0f / fmaxf(g_cnt[gn], 1.0f);
            }
#pragma unroll
            for (int q = 0; q < 8; q++) {
                float4 v = __ldg(g4 + q);
                v.x *= scale; v.y *= scale; v.z *= scale; v.w *= scale;
                int c = hh * 32 + q * 4;
                *(u32*)(smem + N_A0 + (rr * SA + c) * 2) = pack2h(v.x, v.y);
                *(u32*)(smem + N_A0 + (rr * SA + c + 2) * 2) = pack2h(v.z, v.w);
            }
        }
        __syncthreads();

        bool valid = (base + row) < (size_t)nNodes;

        // ---- L0: K=128 N=128, A0 -> A1 ----
        mma_half(smem, N_A0, N_W0, row0, 128, 136, h * 64, 4, acc);
#pragma unroll
        for (int n = 0; n < 4; n++) {
            wmma::store_matrix_sync(stg, acc[n], 20, wmma::mem_row_major);
            __syncwarp();
            int col = h * 64 + n * 16 + c0;
            float v[8];
#pragma unroll
            for (int j = 0; j < 8; j++) v[j] = sp(stg[r * 20 + c0 + j] + s_cn[col + j]);
            store_A8(smem, N_A1, row, col, v);
            __syncwarp();
        }
        __syncthreads();

        // ---- L1: K=128 N=128, A1 -> A0 ----
        mma_half(smem, N_A1, N_W1, row0, 128, 136, h * 64, 4, acc);
#pragma unroll
        for (int n = 0; n < 4; n++) {
            wmma::store_matrix_sync(stg, acc[n], 20, wmma::mem_row_major);
            __syncwarp();
            int col = h * 64 + n * 16 + c0;
            float v[8];
#pragma unroll
            for (int j = 0; j < 8; j++) v[j] = sp(stg[r * 20 + c0 + j] + s_b1[col + j]);
            store_A8(smem, N_A0, row, col, v);
            __syncwarp();
        }
        __syncthreads();

        // ---- L2: K=128 N=64, A0 -> global (+uv_reg) ----
        mma_half(smem, N_A0, N_W2, row0, 128, 72, h * 32, 2, acc);
#pragma unroll
        for (int n = 0; n < 2; n++) {
            wmma::store_matrix_sync(stg, acc[n], 20, wmma::mem_row_major);
            __syncwarp();
            int col = h * 32 + n * 16 + c0;
            float v[8];
#pragma unroll
            for (int j = 0; j < 8; j++) v[j] = sp(stg[r * 20 + c0 + j] + s_b2[col + j]);
            if (valid) {
                size_t gidx = (base + row) * 64 + col;
                float4 e0 = __ldg((const float4*)(nf + gidx));
                float4 e1 = __ldg((const float4*)(nf + gidx) + 1);
                float4 o0 = {v[0] + e0.x, v[1] + e0.y, v[2] + e0.z, v[3] + e0.w};
                float4 o1 = {v[4] + e1.x, v[5] + e1.y, v[6] + e1.z, v[7] + e1.w};
                *(float4*)(v_out + gidx) = o0;
                *((float4*)(v_out + gidx) + 1) = o1;
#pragma unroll
                for (int j = 0; j < 8; j++) uv_reg[n * 8 + j] += v[j];
            }
            __syncwarp();
        }
    }

#pragma unroll
    for (int n = 0; n < 2; n++) {
#pragma unroll
        for (int j = 0; j < 8; j++) {
            float s = uv_reg[n * 8 + j];
            s += __shfl_xor_sync(0xFFFFFFFFu, s, 2);
            s += __shfl_xor_sync(0xFFFFFFFFu, s, 4);
            s += __shfl_xor_sync(0xFFFFFFFFu, s, 8);
            s += __shfl_xor_sync(0xFFFFFFFFu, s, 16);
            if ((lane >> 1) == 0)
                atomicAdd(&g_uv[h * 32 + n * 16 + (lane & 1) * 8 + j], s);
        }
    }
}

// ---------------------------------------------------------------------------
__global__ void attr_kernel(const float* __restrict__ ga,
                            const float* __restrict__ w0,
                            const float* __restrict__ b0,
                            const float* __restrict__ w1,
                            const float* __restrict__ b1,
                            const float* __restrict__ w2,
                            const float* __restrict__ b2,
                            float* __restrict__ out, float invE, float invN) {
    __shared__ float x[192], h0[128], h1[128];
    int t = threadIdx.x;
    if (t < 64) {
        x[t]       = g_u_pre[t];
        x[64 + t]  = g_ue[t] * invE;
        x[128 + t] = g_uv[t] * invN;
    }
    __syncthreads();
    float acc = b0[t];
    for (int k = 0; k < 192; k++) acc = fmaf(x[k], w0[k * 128 + t], acc);
    h0[t] = sp(acc);
    __syncthreads();
    acc = b1[t];
    for (int k = 0; k < 128; k++) acc = fmaf(h0[k], w1[k * 128 + t], acc);
    h1[t] = sp(acc);
    __syncthreads();
    if (t < 64) {
        float a = b2[t];
        for (int k = 0; k < 128; k++) a = fmaf(h1[k], w2[k * 64 + t], a);
        out[t] = sp(a) + ga[t];
    }
}

// ---------------------------------------------------------------------------
extern "C" void kernel_launch(void* const* d_in, const int* in_sizes, int n_in,
                              void* d_out, int out_size) {
    const float* edge_feat  = (const float*)d_in[0];
    const float* node_feat  = (const float*)d_in[1];
    const float* graph_attr = (const float*)d_in[2];
    const int*   src        = (const int*)d_in[3];
    const int*   dst        = (const int*)d_in[4];
    const float* pre_edge_w = (const float*)d_in[5];
    const float* pre_edge_b = (const float*)d_in[6];
    const float* pre_node_w = (const float*)d_in[7];
    const float* pre_node_b = (const float*)d_in[8];
    const float* pre_attr_w = (const float*)d_in[9];
    const float* pre_attr_b = (const float*)d_in[10];
    const float* edge_w0 = (const float*)d_in[11];
    const float* edge_b0 = (const float*)d_in[12];
    const float* edge_w1 = (const float*)d_in[13];
    const float* edge_b1 = (const float*)d_in[14];
    const float* edge_w2 = (const float*)d_in[15];
    const float* edge_b2 = (const float*)d_in[16];
    const float* node_w0 = (const float*)d_in[17];
    const float* node_b0 = (const float*)d_in[18];
    const float* node_w1 = (const float*)d_in[19];
    const float* node_b1 = (const float*)d_in[20];
    const float* node_w2 = (const float*)d_in[21];
    const float* node_b2 = (const float*)d_in[22];
    const float* attr_w0 = (const float*)d_in[23];
    const float* attr_b0 = (const float*)d_in[24];
    const float* attr_w1 = (const float*)d_in[25];
    const float* attr_b1 = (const float*)d_in[26];
    const float* attr_w2 = (const float*)d_in[27];
    const float* attr_b2 = (const float*)d_in[28];

    float* out = (float*)d_out;
    int E = in_sizes[3];
    int N = in_sizes[1] / 64;
    int eTiles = E / 128;
    int nTiles = (N + 127) / 128;

    cudaFuncSetAttribute(edge_kernel, cudaFuncAttributeMaxDynamicSharedMemorySize,
                         E_TOTAL);
    cudaFuncSetAttribute(node_kernel, cudaFuncAttributeMaxDynamicSharedMemorySize,
                         N_TOTAL);

    zero_kernel<<<256, 256>>>(N);
    pre_attr_kernel<<<1, 64>>>(graph_attr, pre_attr_w, pre_attr_b);
    const_kernel<<<1, 128>>>(edge_w0, edge_b0, node_w0, node_b0);
    prep_w_kernel<<<64, 256>>>(pre_edge_w, edge_w0, edge_w1, edge_w2, node_w0,
                               node_w1, node_w2);
    pre_nodeA_kernel<<<N / 32, 128>>>(node_feat, pre_node_w, pre_node_b, edge_w0);
    edge_kernel<<<NUM_CTAS, 512, E_TOTAL>>>(edge_feat, src, dst, pre_edge_b,
                                            edge_b1, edge_b2, out, eTiles);
    node_kernel<<<NUM_CTAS, 512, N_TOTAL>>>(node_feat, node_b1, node_b2,
                                            out + (size_t)E * 64, N, nTiles);
    attr_kernel<<<1, 128>>>(graph_attr, attr_w0, attr_b0, attr_w1, attr_b1,
                            attr_w2, attr_b2,
                            out + (size_t)E * 64 + (size_t)N * 64,
                            1.0f / (float)E, 1.0f / (float)N);
}

// round 14
// speedup vs baseline: 1.1572x; 1.1572x over previous
#include <cuda_runtime.h>
#include <cuda_fp16.h>
#include <cstdint>
#include <cstddef>

// ---------------------------------------------------------------------------
// MegNetBlock — persistent direct mma.sync fp16 single-pass, ping-pong bufs.
// N=100000, E=800000, D=64, H=128
// ---------------------------------------------------------------------------

#define NMAX 100000
typedef unsigned int u32;

// ---------------- scratch (device globals) ----------------
__device__ float  g_v_pre[NMAX * 64];
__device__ float4 g_As[NMAX * 32];
__device__ float4 g_Ad[NMAX * 32];
__device__ float  g_ve[NMAX * 64];
__device__ float  g_cnt[NMAX];
__device__ float  g_u_pre[64];
__device__ __align__(16) float g_ce[128];
__device__ __align__(16) float g_cn[128];
__device__ float  g_ue[64];
__device__ float  g_uv[64];

// fp16 weights, [k][n] row-major per segment (offsets in elems)
//  0 Wp 0 (64x64) | 1 W0e 4096 (64x128) | 2 W1e 12288 (128x128)
//  3 W2e 28672 (128x64) | 4 W0n 36864 | 5 W1n 53248 | 6 W2n 69632
__device__ __align__(16) __half g_W[77824];

// ---------------- smem layouts (byte offsets) ----------------
static constexpr int SA = 136;   // A row stride in fp16 elems

// edge kernel (512 threads, 16 warps, 128 rows/iter)
static constexpr int E_WP  = 0;        // 64x72   = 9216
static constexpr int E_W0  = 9216;     // 64x136  = 17408
static constexpr int E_W1  = 26624;    // 128x136 = 34816
static constexpr int E_W2  = 61440;    // 128x72  = 18432
static constexpr int E_A0  = 79872;    // 128x136 fp16 = 34816
static constexpr int E_A1  = 114688;   // 34816
static constexpr int E_MISC = 149504;  // src 512|dst 512|pb 256|b1 512|b2 256|ce 512|spart 2048
static constexpr int E_TOTAL = 154112;

// node kernel (512 threads, 128 rows/iter)
static constexpr int N_W0  = 0;        // 34816
static constexpr int N_W1  = 34816;    // 34816
static constexpr int N_W2  = 69632;    // 18432
static constexpr int N_A0  = 88064;    // 34816
static constexpr int N_A1  = 122880;   // 34816
static constexpr int N_MISC = 157696;  // cn 512|b1 512|b2 256|spart 2048
static constexpr int N_TOTAL = 161024;

static constexpr int NUM_CTAS = 148;

// ---------------- helpers ----------------
__device__ __forceinline__ float sp(float x) {
    return fmaxf(x, 0.0f) + __logf(1.0f + __expf(-fabsf(x)));
}
__device__ __forceinline__ u32 pack2h(float a, float b) {
    __half2 h = __floats2half2_rn(a, b);
    return *(u32*)&h;
}
__device__ __forceinline__ u32 s2u(const void* p) {
    return (u32)__cvta_generic_to_shared(p);
}
__device__ __forceinline__ void ldsm_x4(u32 addr, u32* a) {
    asm volatile("ldmatrix.sync.aligned.m8n8.x4.shared.b16 {%0,%1,%2,%3},[%4];"
                 : "=r"(a[0]), "=r"(a[1]), "=r"(a[2]), "=r"(a[3]) : "r"(addr));
}
__device__ __forceinline__ void ldsm_x2t(u32 addr, u32* b) {
    asm volatile("ldmatrix.sync.aligned.m8n8.x2.trans.shared.b16 {%0,%1},[%2];"
                 : "=r"(b[0]), "=r"(b[1]) : "r"(addr));
}
__device__ __forceinline__ void mma16816(float* c, const u32* a, const u32* b) {
    asm volatile(
        "mma.sync.aligned.m16n8k16.row.col.f32.f16.f16.f32 "
        "{%0,%1,%2,%3},{%4,%5,%6,%7},{%8,%9},{%0,%1,%2,%3};"
        : "+f"(c[0]), "+f"(c[1]), "+f"(c[2]), "+f"(c[3])
        : "r"(a[0]), "r"(a[1]), "r"(a[2]), "r"(a[3]), "r"(b[0]), "r"(b[1]));
}

// one warp: C[row0:16, colbase..colbase+8*NT8] = A[row0:, :K] @ W[:K, cols]
// C layout per m16n8 tile i: thread (g=lane>>2, t=lane&3) owns
//   c[i][0]=(row0+g,   col) c[i][1]=(row0+g,   col+1)
//   c[i][2]=(row0+g+8, col) c[i][3]=(row0+g+8, col+1),  col = colbase+8i+2t
template <int K, int NT8>
__device__ __forceinline__ void mma_phase(const char* smem, int offA, int offW,
                                          int SW, int row0, int colbase, int lane,
                                          float c[][4]) {
#pragma unroll
    for (int i = 0; i < NT8; i++) {
        c[i][0] = 0.0f; c[i][1] = 0.0f; c[i][2] = 0.0f; c[i][3] = 0.0f;
    }
    const __half* A = (const __half*)(smem + offA);
    const __half* W = (const __half*)(smem + offW);
    const __half* arow = A + (row0 + (lane & 15)) * SA + ((lane >> 4) << 3);
    const __half* brow = W + (lane & 15) * SW + colbase;
#pragma unroll
    for (int k = 0; k < K; k += 16) {
        u32 a[4];
        ldsm_x4(s2u(arow + k), a);
#pragma unroll
        for (int i = 0; i < NT8; i++) {
            u32 b[2];
            ldsm_x2t(s2u(brow + k * SW + 8 * i), b);
            mma16816(c[i], a, b);
        }
    }
}

__device__ __forceinline__ void load_W_seg(char* smem, int goff, int K, int N, int SW,
                                           int off, int tid, int nthr) {
    const u32* gw = (const u32*)(g_W + goff);
    int total2 = K * N / 2;
    for (int i2 = tid; i2 < total2; i2 += nthr) {
        int k = (2 * i2) / N, n = (2 * i2) % N;
        *(u32*)(smem + off + (k * SW + n) * 2) = gw[i2];
    }
}

// bias + softplus + pack to next A buffer (2 rows x 2 cols per thread)
__device__ __forceinline__ void epi_store(char* smem, int offA, int rA, int rB,
                                          int col, const float* c,
                                          const float* bias) {
    float v0 = sp(c[0] + bias[col]);
    float v1 = sp(c[1] + bias[col + 1]);
    float v2 = sp(c[2] + bias[col]);
    float v3 = sp(c[3] + bias[col + 1]);
    *(u32*)(smem + offA + (rA * SA + col) * 2) = pack2h(v0, v1);
    *(u32*)(smem + offA + (rB * SA + col) * 2) = pack2h(v2, v3);
}

// ---------------------------------------------------------------------------
__global__ void zero_kernel(int nNodes) {
    int total = nNodes * 64 + nNodes + 128;
    for (int i = blockIdx.x * blockDim.x + threadIdx.x; i < total;
         i += gridDim.x * blockDim.x) {
        if (i < nNodes * 64) g_ve[i] = 0.0f;
        else if (i < nNodes * 64 + nNodes) g_cnt[i - nNodes * 64] = 0.0f;
        else {
            int j = i - nNodes * 64 - nNodes;
            if (j < 64) g_ue[j] = 0.0f; else g_uv[j - 64] = 0.0f;
        }
    }
}

__global__ void pre_attr_kernel(const float* __restrict__ ga,
                                const float* __restrict__ w,
                                const float* __restrict__ b) {
    __shared__ float sg[64];
    int t = threadIdx.x;
    sg[t] = ga[t];
    __syncthreads();
    float acc = b[t];
    for (int k = 0; k < 64; k++) acc = fmaf(sg[k], w[k * 64 + t], acc);
    g_u_pre[t] = sp(acc);
}

__global__ void const_kernel(const float* __restrict__ ew0,
                             const float* __restrict__ eb0,
                             const float* __restrict__ nw0,
                             const float* __restrict__ nb0) {
    __shared__ float su[64];
    int t = threadIdx.x;  // 128
    if (t < 64) su[t] = g_u_pre[t];
    __syncthreads();
    float a = eb0[t], c = nb0[t];
    for (int k = 0; k < 64; k++) {
        a = fmaf(su[k], ew0[(192 + k) * 128 + t], a);
        c = fmaf(su[k], nw0[(128 + k) * 128 + t], c);
    }
    g_ce[t] = a;
    g_cn[t] = c;
}

__global__ void prep_w_kernel(const float* pw, const float* ew0,
                              const float* ew1, const float* ew2,
                              const float* nw0, const float* nw1,
                              const float* nw2) {
    const float* srcs[7] = {pw, ew0 + 128 * 128, ew1, ew2, nw0, nw1, nw2};
    const int KN[7] = {4096, 8192, 16384, 8192, 16384, 16384, 8192};
    const int off[7] = {0, 4096, 12288, 28672, 36864, 53248, 69632};
#pragma unroll 1
    for (int s = 0; s < 7; s++) {
        const float* sc = srcs[s];
        for (int i = blockIdx.x * blockDim.x + threadIdx.x; i < KN[s];
             i += gridDim.x * blockDim.x)
            g_W[off[s] + i] = __float2half_rn(sc[i]);
    }
}

// ---------------------------------------------------------------------------
__global__ __launch_bounds__(128) void pre_nodeA_kernel(
    const float* __restrict__ nf, const float* __restrict__ pw,
    const float* __restrict__ pb, const float* __restrict__ ew0) {
    __shared__ float snf[2048];
    __shared__ float sv[2048];
    int tid = threadIdx.x;
    size_t base = (size_t)blockIdx.x * 32;

    for (int i = tid; i < 512; i += 128)
        ((float4*)snf)[i] = ((const float4*)(nf + base * 64))[i];
    __syncthreads();

    {
        int col = tid & 63, hf = tid >> 6;
        float bb = pb[col];
        float acc[16];
#pragma unroll
        for (int i = 0; i < 16; i++) acc[i] = bb;
        const float* xr = snf + hf * 16 * 64;
        for (int k = 0; k < 64; k += 4) {
            float wa = __ldg(pw + k * 64 + col), wb = __ldg(pw + (k + 1) * 64 + col);
            float wc = __ldg(pw + (k + 2) * 64 + col), wd = __ldg(pw + (k + 3) * 64 + col);
#pragma unroll
            for (int i = 0; i < 16; i++) {
                float4 xv = *(const float4*)(xr + i * 64 + k);
                acc[i] = fmaf(xv.x, wa, acc[i]);
                acc[i] = fmaf(xv.y, wb, acc[i]);
                acc[i] = fmaf(xv.z, wc, acc[i]);
                acc[i] = fmaf(xv.w, wd, acc[i]);
            }
        }
#pragma unroll
        for (int i = 0; i < 16; i++) {
            float v = sp(acc[i]);
            sv[(hf * 16 + i) * 64 + col] = v;
            g_v_pre[(base + hf * 16 + i) * 64 + col] = v;
        }
    }
    __syncthreads();

    float* Asf = (float*)g_As;
    float* Adf = (float*)g_Ad;
    int j = tid;
#pragma unroll 1
    for (int m = 0; m < 2; m++) {
        const float* w = ew0 + (size_t)m * 64 * 128;
        float acc[32];
#pragma unroll
        for (int e = 0; e < 32; e++) acc[e] = 0.0f;
        for (int k = 0; k < 64; k += 4) {
            float wa = __ldg(w + k * 128 + j), wb = __ldg(w + (k + 1) * 128 + j);
            float wc = __ldg(w + (k + 2) * 128 + j), wd = __ldg(w + (k + 3) * 128 + j);
#pragma unroll
            for (int e = 0; e < 32; e++) {
                float4 xv = *(const float4*)(sv + e * 64 + k);
                acc[e] = fmaf(xv.x, wa, acc[e]);
                acc[e] = fmaf(xv.y, wb, acc[e]);
                acc[e] = fmaf(xv.z, wc, acc[e]);
                acc[e] = fmaf(xv.w, wd, acc[e]);
            }
        }
        float* dstp = m ? Adf : Asf;
#pragma unroll
        for (int e = 0; e < 32; e++) dstp[(base + e) * 128 + j] = acc[e];
    }
}

// ---------------------------------------------------------------------------
// persistent edge kernel: 128 edges / iteration, 512 threads / 16 warps.
// warp (slab 0..7, h 0..1): rows slab*16..+16, cols h*(N/2)..
// ping-pong: p0 A0->A1, p1 A1->A0, p2 A0->A1, p3 A1->global (+fstage A0)
// ---------------------------------------------------------------------------
__global__ __launch_bounds__(512) void edge_kernel(
    const float* __restrict__ ef, const int* __restrict__ srcI,
    const int* __restrict__ dstI, const float* __restrict__ pb,
    const float* __restrict__ b1, const float* __restrict__ b2,
    float* __restrict__ e_out, int nTiles) {
    extern __shared__ char smem[];
    int tid = threadIdx.x, wid = tid >> 5, lane = tid & 31;

    int*   s_src = (int*)(smem + E_MISC);
    int*   s_dst = (int*)(smem + E_MISC + 512);
    float* s_pb  = (float*)(smem + E_MISC + 1024);
    float* s_b1  = (float*)(smem + E_MISC + 1280);
    float* s_b2  = (float*)(smem + E_MISC + 1792);
    float* s_ce  = (float*)(smem + E_MISC + 2048);
    float* spart = (float*)(smem + E_MISC + 2560);
    float* fstage = (float*)(smem + E_A0);  // f32 [128][68]

    load_W_seg(smem, 0,     64, 64,  72, E_WP, tid, 512);
    load_W_seg(smem, 4096,  64, 128, 136, E_W0, tid, 512);
    load_W_seg(smem, 12288, 128, 128, 136, E_W1, tid, 512);
    load_W_seg(smem, 28672, 128, 64,  72, E_W2, tid, 512);
    if (tid < 128) {
        s_ce[tid] = g_ce[tid];
        s_b1[tid] = __ldg(b1 + tid);
    } else if (tid < 192) {
        s_pb[tid - 128] = __ldg(pb + tid - 128);
    } else if (tid < 256) {
        s_b2[tid - 192] = __ldg(b2 + tid - 192);
    }

    int slab = wid & 7, h = wid >> 3, row0 = slab * 16;
    int g = lane >> 2, t2 = (lane & 3) * 2;
    int rA = row0 + g, rB = row0 + g + 8;
    float ue_acc = 0.0f;
    float c[8][4];

    for (int tt = blockIdx.x; tt < nTiles; tt += gridDim.x) {
        size_t base = (size_t)tt * 128;
        __syncthreads();  // prev iter done (p3 read A1/s_dst, spart consumed)

        if (tid < 128) {
            s_src[tid] = srcI[base + tid];
            s_dst[tid] = dstI[base + tid];
        }
        // stage ef -> A0: 2048 float4s
        for (int i = tid; i < 2048; i += 512) {
            int rr = i >> 4, q = i & 15;
            float4 v = __ldg((const float4*)(ef + (base + rr) * 64) + q);
            int cc = q * 4;
            *(u32*)(smem + E_A0 + (rr * SA + cc) * 2) = pack2h(v.x, v.y);
            *(u32*)(smem + E_A0 + (rr * SA + cc + 2) * 2) = pack2h(v.z, v.w);
        }
        __syncthreads();

        // ---- phase 0: pre-edge K=64 N=64, A0 -> A1 ----
        mma_phase<64, 4>(smem, E_A0, E_WP, 72, row0, h * 32, lane, c);
        __syncthreads();
#pragma unroll
        for (int n = 0; n < 4; n++)
            epi_store(smem, E_A1, rA, rB, h * 32 + n * 8 + t2, c[n], s_pb);
        __syncthreads();

        // ---- phase 1: L0 K=64 N=128 (+As[src]+Ad[dst]+ce), A1 -> A0 ----
        mma_phase<64, 8>(smem, E_A1, E_W0, 136, row0, h * 64, lane, c);
        __syncthreads();
        {
            const float2* asA = (const float2*)g_As + (size_t)s_src[rA] * 64;
            const float2* adA = (const float2*)g_Ad + (size_t)s_dst[rA] * 64;
            const float2* asB = (const float2*)g_As + (size_t)s_src[rB] * 64;
            const float2* adB = (const float2*)g_Ad + (size_t)s_dst[rB] * 64;
#pragma unroll
            for (int n = 0; n < 8; n++) {
                int col = h * 64 + n * 8 + t2, ci = col >> 1;
                float2 a0 = __ldg(asA + ci), d0 = __ldg(adA + ci);
                float2 a1 = __ldg(asB + ci), d1 = __ldg(adB + ci);
                float v0 = sp(c[n][0] + a0.x + d0.x + s_ce[col]);
                float v1 = sp(c[n][1] + a0.y + d0.y + s_ce[col + 1]);
                float v2 = sp(c[n][2] + a1.x + d1.x + s_ce[col]);
                float v3 = sp(c[n][3] + a1.y + d1.y + s_ce[col + 1]);
                *(u32*)(smem + E_A0 + (rA * SA + col) * 2) = pack2h(v0, v1);
                *(u32*)(smem + E_A0 + (rB * SA + col) * 2) = pack2h(v2, v3);
            }
        }
        __syncthreads();

        // ---- phase 2: L1 K=128 N=128, A0 -> A1 ----
        mma_phase<128, 8>(smem, E_A0, E_W1, 136, row0, h * 64, lane, c);
        __syncthreads();
#pragma unroll
        for (int n = 0; n < 8; n++)
            epi_store(smem, E_A1, rA, rB, h * 64 + n * 8 + t2, c[n], s_b1);
        __syncthreads();

        // ---- phase 3: L2 K=128 N=64, A1 -> global (+fstage A0) ----
        mma_phase<128, 4>(smem, E_A1, E_W2, 72, row0, h * 32, lane, c);
        {
            int dA = s_dst[rA], dB = s_dst[rB];
#pragma unroll
            for (int n = 0; n < 4; n++) {
                int col = h * 32 + n * 8 + t2;
                float v0 = sp(c[n][0] + s_b2[col]);
                float v1 = sp(c[n][1] + s_b2[col + 1]);
                float v2 = sp(c[n][2] + s_b2[col]);
                float v3 = sp(c[n][3] + s_b2[col + 1]);
                size_t gA = (base + rA) * 64 + col, gB = (base + rB) * 64 + col;
                float2 eA = __ldg((const float2*)(ef + gA));
                float2 eB = __ldg((const float2*)(ef + gB));
                float2 oA = {v0 + eA.x, v1 + eA.y};
                float2 oB = {v2 + eB.x, v3 + eB.y};
                *(float2*)(e_out + gA) = oA;
                *(float2*)(e_out + gB) = oB;
                atomicAdd(&g_ve[(size_t)dA * 64 + col], v0);
                atomicAdd(&g_ve[(size_t)dA * 64 + col + 1], v1);
                atomicAdd(&g_ve[(size_t)dB * 64 + col], v2);
                atomicAdd(&g_ve[(size_t)dB * 64 + col + 1], v3);
                fstage[rA * 68 + col] = v0;
                fstage[rA * 68 + col + 1] = v1;
                fstage[rB * 68 + col] = v2;
                fstage[rB * 68 + col + 1] = v3;
                if (n == 0 && h == 0 && t2 == 0) {
                    atomicAdd(&g_cnt[dA], 1.0f);
                    atomicAdd(&g_cnt[dB], 1.0f);
                }
            }
        }
        __syncthreads();

        // ue partial: 512 threads, 16 rows each
        {
            int col = tid & 63, q = tid >> 6;
            float s = 0.0f;
#pragma unroll
            for (int rr = q * 16; rr < q * 16 + 16; rr++) s += fstage[rr * 68 + col];
            spart[tid] = s;
        }
        __syncthreads();
        if (tid < 64) {
            float s = 0.0f;
#pragma unroll
            for (int q = 0; q < 8; q++) s += spart[q * 64 + tid];
            ue_acc += s;
        }
    }
    if (tid < 64) atomicAdd(&g_ue[tid], ue_acc);
}

// ---------------------------------------------------------------------------
// persistent node kernel: 128 nodes / iteration, 512 threads
// ping-pong: L0 A0->A1, L1 A1->A0, L2 A0 -> global (+fstage A1)
// ---------------------------------------------------------------------------
__global__ __launch_bounds__(512) void node_kernel(
    const float* __restrict__ nf, const float* __restrict__ b1,
    const float* __restrict__ b2, float* __restrict__ v_out, int nNodes,
    int nTiles) {
    extern __shared__ char smem[];
    int tid = threadIdx.x, wid = tid >> 5, lane = tid & 31;

    float* s_cn  = (float*)(smem + N_MISC);
    float* s_b1  = (float*)(smem + N_MISC + 512);
    float* s_b2  = (float*)(smem + N_MISC + 1024);
    float* spart = (float*)(smem + N_MISC + 1280);
    float* fstage = (float*)(smem + N_A1);

    load_W_seg(smem, 36864, 128, 128, 136, N_W0, tid, 512);
    load_W_seg(smem, 53248, 128, 128, 136, N_W1, tid, 512);
    load_W_seg(smem, 69632, 128, 64,  72, N_W2, tid, 512);
    if (tid < 128) {
        s_cn[tid] = g_cn[tid];
        s_b1[tid] = __ldg(b1 + tid);
    } else if (tid < 192) {
        s_b2[tid - 128] = (tid - 128 < 64) ? __ldg(b2 + tid - 128) : 0.0f;
    }

    int slab = wid & 7, h = wid >> 3, row0 = slab * 16;
    int g = lane >> 2, t2 = (lane & 3) * 2;
    int rA = row0 + g, rB = row0 + g + 8;
    float uv_acc = 0.0f;
    float c[8][4];

    for (int tt = blockIdx.x; tt < nTiles; tt += gridDim.x) {
        size_t base = (size_t)tt * 128;
        __syncthreads();

        // stage X = [v_pre | ve_mean] (K=128) -> A0
        {
            int rr = tid & 127, hh = tid >> 7;  // hh 0..3
            size_t gn = base + rr;
            if (gn >= (size_t)nNodes) gn = nNodes - 1;
            const float4* g4;
            float scale = 1.0f;
            if (hh < 2) {
                g4 = (const float4*)(g_v_pre + gn * 64) + hh * 8;
            } else {
                g4 = (const float4*)(g_ve + gn * 64) + (hh - 2) * 8;
                scale = 1.0f / fmaxf(g_cnt[gn], 1.0f);
            }
#pragma unroll
            for (int q = 0; q < 8; q++) {
                float4 v = __ldg(g4 + q);
                v.x *= scale; v.y *= scale; v.z *= scale; v.w *= scale;
                int cc = hh * 32 + q * 4;
                *(u32*)(smem + N_A0 + (rr * SA + cc) * 2) = pack2h(v.x, v.y);
                *(u32*)(smem + N_A0 + (rr * SA + cc + 2) * 2) = pack2h(v.z, v.w);
            }
        }
        __syncthreads();

        bool vA = (base + rA) < (size_t)nNodes;
        bool vB = (base + rB) < (size_t)nNodes;

        // ---- L0: K=128 N=128, A0 -> A1 ----
        mma_phase<128, 8>(smem, N_A0, N_W0, 136, row0, h * 64, lane, c);
        __syncthreads();
#pragma unroll
        for (int n = 0; n < 8; n++)
            epi_store(smem, N_A1, rA, rB, h * 64 + n * 8 + t2, c[n], s_cn);
        __syncthreads();

        // ---- L1: K=128 N=128, A1 -> A0 ----
        mma_phase<128, 8>(smem, N_A1, N_W1, 136, row0, h * 64, lane, c);
        __syncthreads();
#pragma unroll
        for (int n = 0; n < 8; n++)
            epi_store(smem, N_A0, rA, rB, h * 64 + n * 8 + t2, c[n], s_b1);
        __syncthreads();

        // ---- L2: K=128 N=64, A0 -> global (+fstage A1) ----
        mma_phase<128, 4>(smem, N_A0, N_W2, 72, row0, h * 32, lane, c);
#pragma unroll
        for (int n = 0; n < 4; n++) {
            int col = h * 32 + n * 8 + t2;
            float v0 = sp(c[n][0] + s_b2[col]);
            float v1 = sp(c[n][1] + s_b2[col + 1]);
            float v2 = sp(c[n][2] + s_b2[col]);
            float v3 = sp(c[n][3] + s_b2[col + 1]);
            if (vA) {
                size_t gA = (base + rA) * 64 + col;
                float2 eA = __ldg((const float2*)(nf + gA));
                float2 oA = {v0 + eA.x, v1 + eA.y};
                *(float2*)(v_out + gA) = oA;
            }
            if (vB) {
                size_t gB = (base + rB) * 64 + col;
                float2 eB = __ldg((const float2*)(nf + gB));
                float2 oB = {v2 + eB.x, v3 + eB.y};
                *(float2*)(v_out + gB) = oB;
            }
            fstage[rA * 68 + col] = vA ? v0 : 0.0f;
            fstage[rA * 68 + col + 1] = vA ? v1 : 0.0f;
            fstage[rB * 68 + col] = vB ? v2 : 0.0f;
            fstage[rB * 68 + col + 1] = vB ? v3 : 0.0f;
        }
        __syncthreads();

        {
            int col = tid & 63, q = tid >> 6;
            float s = 0.0f;
#pragma unroll
            for (int rr = q * 16; rr < q * 16 + 16; rr++) s += fstage[rr * 68 + col];
            spart[tid] = s;
        }
        __syncthreads();
        if (tid < 64) {
            float s = 0.0f;
#pragma unroll
            for (int q = 0; q < 8; q++) s += spart[q * 64 + tid];
            uv_acc += s;
        }
    }
    if (tid < 64) atomicAdd(&g_uv[tid], uv_acc);
}

// ---------------------------------------------------------------------------
__global__ void attr_kernel(const float* __restrict__ ga,
                            const float* __restrict__ w0,
                            const float* __restrict__ b0,
                            const float* __restrict__ w1,
                            const float* __restrict__ b1,
                            const float* __restrict__ w2,
                            const float* __restrict__ b2,
                            float* __restrict__ out, float invE, float invN) {
    __shared__ float x[192], h0[128], h1[128];
    int t = threadIdx.x;
    if (t < 64) {
        x[t]       = g_u_pre[t];
        x[64 + t]  = g_ue[t] * invE;
        x[128 + t] = g_uv[t] * invN;
    }
    __syncthreads();
    float acc = b0[t];
    for (int k = 0; k < 192; k++) acc = fmaf(x[k], w0[k * 128 + t], acc);
    h0[t] = sp(acc);
    __syncthreads();
    acc = b1[t];
    for (int k = 0; k < 128; k++) acc = fmaf(h0[k], w1[k * 128 + t], acc);
    h1[t] = sp(acc);
    __syncthreads();
    if (t < 64) {
        float a = b2[t];
        for (int k = 0; k < 128; k++) a = fmaf(h1[k], w2[k * 64 + t], a);
        out[t] = sp(a) + ga[t];
    }
}

// ---------------------------------------------------------------------------
extern "C" void kernel_launch(void* const* d_in, const int* in_sizes, int n_in,
                              void* d_out, int out_size) {
    const float* edge_feat  = (const float*)d_in[0];
    const float* node_feat  = (const float*)d_in[1];
    const float* graph_attr = (const float*)d_in[2];
    const int*   src        = (const int*)d_in[3];
    const int*   dst        = (const int*)d_in[4];
    const float* pre_edge_w = (const float*)d_in[5];
    const float* pre_edge_b = (const float*)d_in[6];
    const float* pre_node_w = (const float*)d_in[7];
    const float* pre_node_b = (const float*)d_in[8];
    const float* pre_attr_w = (const float*)d_in[9];
    const float* pre_attr_b = (const float*)d_in[10];
    const float* edge_w0 = (const float*)d_in[11];
    const float* edge_b0 = (const float*)d_in[12];
    const float* edge_w1 = (const float*)d_in[13];
    const float* edge_b1 = (const float*)d_in[14];
    const float* edge_w2 = (const float*)d_in[15];
    const float* edge_b2 = (const float*)d_in[16];
    const float* node_w0 = (const float*)d_in[17];
    const float* node_b0 = (const float*)d_in[18];
    const float* node_w1 = (const float*)d_in[19];
    const float* node_b1 = (const float*)d_in[20];
    const float* node_w2 = (const float*)d_in[21];
    const float* node_b2 = (const float*)d_in[22];
    const float* attr_w0 = (const float*)d_in[23];
    const float* attr_b0 = (const float*)d_in[24];
    const float* attr_w1 = (const float*)d_in[25];
    const float* attr_b1 = (const float*)d_in[26];
    const float* attr_w2 = (const float*)d_in[27];
    const float* attr_b2 = (const float*)d_in[28];

    float* out = (float*)d_out;
    int E = in_sizes[3];
    int N = in_sizes[1] / 64;
    int eTiles = E / 128;
    int nTiles = (N + 127) / 128;

    cudaFuncSetAttribute(edge_kernel, cudaFuncAttributeMaxDynamicSharedMemorySize,
                         E_TOTAL);
    cudaFuncSetAttribute(node_kernel, cudaFuncAttributeMaxDynamicSharedMemorySize,
                         N_TOTAL);

    zero_kernel<<<256, 256>>>(N);
    pre_attr_kernel<<<1, 64>>>(graph_attr, pre_attr_w, pre_attr_b);
    const_kernel<<<1, 128>>>(edge_w0, edge_b0, node_w0, node_b0);
    prep_w_kernel<<<64, 256>>>(pre_edge_w, edge_w0, edge_w1, edge_w2, node_w0,
                               node_w1, node_w2);
    pre_nodeA_kernel<<<N / 32, 128>>>(node_feat, pre_node_w, pre_node_b, edge_w0);
    edge_kernel<<<NUM_CTAS, 512, E_TOTAL>>>(edge_feat, src, dst, pre_edge_b,
                                            edge_b1, edge_b2, out, eTiles);
    node_kernel<<<NUM_CTAS, 512, N_TOTAL>>>(node_feat, node_b1, node_b2,
                                            out + (size_t)E * 64, N, nTiles);
    attr_kernel<<<1, 128>>>(graph_attr, attr_w0, attr_b0, attr_w1, attr_b1,
                            attr_w2, attr_b2,
                            out + (size_t)E * 64 + (size_t)N * 64,
                            1.0f / (float)E, 1.0f / (float)N);
}

// round 15
// speedup vs baseline: 1.2002x; 1.0372x over previous
#include <cuda_runtime.h>
#include <cuda_fp16.h>
#include <cstdint>
#include <cstddef>

// ---------------------------------------------------------------------------
// MegNetBlock — persistent direct mma.sync fp16, x4 B-ldmatrix, v2 red,
// minimal syncs.  N=100000, E=800000, D=64, H=128
// ---------------------------------------------------------------------------

#define NMAX 100000
typedef unsigned int u32;

// ---------------- scratch (device globals) ----------------
__device__ float  g_v_pre[NMAX * 64];
__device__ float4 g_As[NMAX * 32];
__device__ float4 g_Ad[NMAX * 32];
__device__ float  g_ve[NMAX * 64];
__device__ float  g_cnt[NMAX];
__device__ float  g_u_pre[64];
__device__ __align__(16) float g_ce[128];
__device__ __align__(16) float g_cn[128];
__device__ float  g_ue[64];
__device__ float  g_uv[64];

// fp16 weights, [k][n] row-major per segment (offsets in elems)
__device__ __align__(16) __half g_W[77824];

// ---------------- smem layouts (byte offsets) ----------------
static constexpr int SA = 136;   // A row stride in fp16 elems

// edge kernel (512 threads, 16 warps, 128 rows/iter)
static constexpr int E_WP  = 0;        // 64x72
static constexpr int E_W0  = 9216;     // 64x136
static constexpr int E_W1  = 26624;    // 128x136
static constexpr int E_W2  = 61440;    // 128x72
static constexpr int E_A0  = 79872;    // 128x136 fp16
static constexpr int E_A1  = 114688;
static constexpr int E_MISC = 149504;  // src|dst|pb|b1|b2|ce|spart
static constexpr int E_TOTAL = 154112;

// node kernel (512 threads, 128 rows/iter)
static constexpr int N_W0  = 0;
static constexpr int N_W1  = 34816;
static constexpr int N_W2  = 69632;
static constexpr int N_A0  = 88064;
static constexpr int N_A1  = 122880;
static constexpr int N_MISC = 157696;
static constexpr int N_TOTAL = 161024;

static constexpr int NUM_CTAS = 148;

// ---------------- helpers ----------------
__device__ __forceinline__ float sp(float x) {
    return fmaxf(x, 0.0f) + __logf(1.0f + __expf(-fabsf(x)));
}
__device__ __forceinline__ u32 pack2h(float a, float b) {
    __half2 h = __floats2half2_rn(a, b);
    return *(u32*)&h;
}
__device__ __forceinline__ u32 s2u(const void* p) {
    return (u32)__cvta_generic_to_shared(p);
}
__device__ __forceinline__ void ldsm_x4(u32 addr, u32* a) {
    asm volatile("ldmatrix.sync.aligned.m8n8.x4.shared.b16 {%0,%1,%2,%3},[%4];"
                 : "=r"(a[0]), "=r"(a[1]), "=r"(a[2]), "=r"(a[3]) : "r"(addr));
}
__device__ __forceinline__ void ldsm_x4t(u32 addr, u32* b) {
    asm volatile("ldmatrix.sync.aligned.m8n8.x4.trans.shared.b16 {%0,%1,%2,%3},[%4];"
                 : "=r"(b[0]), "=r"(b[1]), "=r"(b[2]), "=r"(b[3]) : "r"(addr));
}
__device__ __forceinline__ void mma16816(float* c, const u32* a, const u32* b) {
    asm volatile(
        "mma.sync.aligned.m16n8k16.row.col.f32.f16.f16.f32 "
        "{%0,%1,%2,%3},{%4,%5,%6,%7},{%8,%9},{%0,%1,%2,%3};"
        : "+f"(c[0]), "+f"(c[1]), "+f"(c[2]), "+f"(c[3])
        : "r"(a[0]), "r"(a[1]), "r"(a[2]), "r"(a[3]), "r"(b[0]), "r"(b[1]));
}
__device__ __forceinline__ void red2(float* p, float a, float b) {
    asm volatile("red.global.add.v2.f32 [%0],{%1,%2};"
                 :: "l"(p), "f"(a), "f"(b) : "memory");
}

// one warp: C[row0:16, colbase..colbase+8*NT8] = A[row0:, :K] @ W[:K, cols]
// C tile i: thread (g=lane>>2, t=lane&3) owns rows row0+g / row0+g+8,
// cols colbase+8i+2t .. +1.  B loaded two tiles per ldsm.x4.trans.
template <int K, int NT8>
__device__ __forceinline__ void mma_phase(const char* smem, int offA, int offW,
                                          int SW, int row0, int colbase, int lane,
                                          float c[][4]) {
#pragma unroll
    for (int i = 0; i < NT8; i++) {
        c[i][0] = 0.0f; c[i][1] = 0.0f; c[i][2] = 0.0f; c[i][3] = 0.0f;
    }
    const __half* A = (const __half*)(smem + offA);
    const __half* W = (const __half*)(smem + offW);
    const __half* arow = A + (row0 + (lane & 15)) * SA + ((lane >> 4) << 3);
    int q = lane >> 3, rw = lane & 7;
    const __half* brow = W + ((q & 1) * 8 + rw) * SW + colbase + (q >> 1) * 8;
#pragma unroll
    for (int k = 0; k < K; k += 16) {
        u32 a[4];
        ldsm_x4(s2u(arow + k), a);
#pragma unroll
        for (int i2 = 0; i2 < NT8 / 2; i2++) {
            u32 b[4];
            ldsm_x4t(s2u(brow + k * SW + i2 * 16), b);
            mma16816(c[2 * i2], a, b);
            mma16816(c[2 * i2 + 1], a, b + 2);
        }
    }
}

__device__ __forceinline__ void load_W_seg(char* smem, int goff, int K, int N, int SW,
                                           int off, int tid, int nthr) {
    const u32* gw = (const u32*)(g_W + goff);
    int total2 = K * N / 2;
    for (int i2 = tid; i2 < total2; i2 += nthr) {
        int k = (2 * i2) / N, n = (2 * i2) % N;
        *(u32*)(smem + off + (k * SW + n) * 2) = gw[i2];
    }
}

__device__ __forceinline__ void epi_store(char* smem, int offA, int rA, int rB,
                                          int col, const float* c,
                                          const float* bias) {
    float v0 = sp(c[0] + bias[col]);
    float v1 = sp(c[1] + bias[col + 1]);
    float v2 = sp(c[2] + bias[col]);
    float v3 = sp(c[3] + bias[col + 1]);
    *(u32*)(smem + offA + (rA * SA + col) * 2) = pack2h(v0, v1);
    *(u32*)(smem + offA + (rB * SA + col) * 2) = pack2h(v2, v3);
}

// ---------------------------------------------------------------------------
__global__ void zero_kernel(int nNodes) {
    int total = nNodes * 64 + nNodes + 128;
    for (int i = blockIdx.x * blockDim.x + threadIdx.x; i < total;
         i += gridDim.x * blockDim.x) {
        if (i < nNodes * 64) g_ve[i] = 0.0f;
        else if (i < nNodes * 64 + nNodes) g_cnt[i - nNodes * 64] = 0.0f;
        else {
            int j = i - nNodes * 64 - nNodes;
            if (j < 64) g_ue[j] = 0.0f; else g_uv[j - 64] = 0.0f;
        }
    }
}

__global__ void pre_attr_kernel(const float* __restrict__ ga,
                                const float* __restrict__ w,
                                const float* __restrict__ b) {
    __shared__ float sg[64];
    int t = threadIdx.x;
    sg[t] = ga[t];
    __syncthreads();
    float acc = b[t];
    for (int k = 0; k < 64; k++) acc = fmaf(sg[k], w[k * 64 + t], acc);
    g_u_pre[t] = sp(acc);
}

__global__ void const_kernel(const float* __restrict__ ew0,
                             const float* __restrict__ eb0,
                             const float* __restrict__ nw0,
                             const float* __restrict__ nb0) {
    __shared__ float su[64];
    int t = threadIdx.x;  // 128
    if (t < 64) su[t] = g_u_pre[t];
    __syncthreads();
    float a = eb0[t], c = nb0[t];
    for (int k = 0; k < 64; k++) {
        a = fmaf(su[k], ew0[(192 + k) * 128 + t], a);
        c = fmaf(su[k], nw0[(128 + k) * 128 + t], c);
    }
    g_ce[t] = a;
    g_cn[t] = c;
}

__global__ void prep_w_kernel(const float* pw, const float* ew0,
                              const float* ew1, const float* ew2,
                              const float* nw0, const float* nw1,
                              const float* nw2) {
    const float* srcs[7] = {pw, ew0 + 128 * 128, ew1, ew2, nw0, nw1, nw2};
    const int KN[7] = {4096, 8192, 16384, 8192, 16384, 16384, 8192};
    const int off[7] = {0, 4096, 12288, 28672, 36864, 53248, 69632};
#pragma unroll 1
    for (int s = 0; s < 7; s++) {
        const float* sc = srcs[s];
        for (int i = blockIdx.x * blockDim.x + threadIdx.x; i < KN[s];
             i += gridDim.x * blockDim.x)
            g_W[off[s] + i] = __float2half_rn(sc[i]);
    }
}

// ---------------------------------------------------------------------------
__global__ __launch_bounds__(128) void pre_nodeA_kernel(
    const float* __restrict__ nf, const float* __restrict__ pw,
    const float* __restrict__ pb, const float* __restrict__ ew0) {
    __shared__ float snf[2048];
    __shared__ float sv[2048];
    int tid = threadIdx.x;
    size_t base = (size_t)blockIdx.x * 32;

    for (int i = tid; i < 512; i += 128)
        ((float4*)snf)[i] = ((const float4*)(nf + base * 64))[i];
    __syncthreads();

    {
        int col = tid & 63, hf = tid >> 6;
        float bb = pb[col];
        float acc[16];
#pragma unroll
        for (int i = 0; i < 16; i++) acc[i] = bb;
        const float* xr = snf + hf * 16 * 64;
        for (int k = 0; k < 64; k += 4) {
            float wa = __ldg(pw + k * 64 + col), wb = __ldg(pw + (k + 1) * 64 + col);
            float wc = __ldg(pw + (k + 2) * 64 + col), wd = __ldg(pw + (k + 3) * 64 + col);
#pragma unroll
            for (int i = 0; i < 16; i++) {
                float4 xv = *(const float4*)(xr + i * 64 + k);
                acc[i] = fmaf(xv.x, wa, acc[i]);
                acc[i] = fmaf(xv.y, wb, acc[i]);
                acc[i] = fmaf(xv.z, wc, acc[i]);
                acc[i] = fmaf(xv.w, wd, acc[i]);
            }
        }
#pragma unroll
        for (int i = 0; i < 16; i++) {
            float v = sp(acc[i]);
            sv[(hf * 16 + i) * 64 + col] = v;
            g_v_pre[(base + hf * 16 + i) * 64 + col] = v;
        }
    }
    __syncthreads();

    float* Asf = (float*)g_As;
    float* Adf = (float*)g_Ad;
    int j = tid;
#pragma unroll 1
    for (int m = 0; m < 2; m++) {
        const float* w = ew0 + (size_t)m * 64 * 128;
        float acc[32];
#pragma unroll
        for (int e = 0; e < 32; e++) acc[e] = 0.0f;
        for (int k = 0; k < 64; k += 4) {
            float wa = __ldg(w + k * 128 + j), wb = __ldg(w + (k + 1) * 128 + j);
            float wc = __ldg(w + (k + 2) * 128 + j), wd = __ldg(w + (k + 3) * 128 + j);
#pragma unroll
            for (int e = 0; e < 32; e++) {
                float4 xv = *(const float4*)(sv + e * 64 + k);
                acc[e] = fmaf(xv.x, wa, acc[e]);
                acc[e] = fmaf(xv.y, wb, acc[e]);
                acc[e] = fmaf(xv.z, wc, acc[e]);
                acc[e] = fmaf(xv.w, wd, acc[e]);
            }
        }
        float* dstp = m ? Adf : Asf;
#pragma unroll
        for (int e = 0; e < 32; e++) dstp[(base + e) * 128 + j] = acc[e];
    }
}

// ---------------------------------------------------------------------------
// persistent edge kernel: 128 edges/iter, 512 threads, 6 syncs/iter.
// ping-pong: p0 A0->A1, p1 A1->A0, p2 A0->A1, p3 A1->global (+fstage A0)
// ---------------------------------------------------------------------------
__global__ __launch_bounds__(512) void edge_kernel(
    const float* __restrict__ ef, const int* __restrict__ srcI,
    const int* __restrict__ dstI, const float* __restrict__ pb,
    const float* __restrict__ b1, const float* __restrict__ b2,
    float* __restrict__ e_out, int nTiles) {
    extern __shared__ char smem[];
    int tid = threadIdx.x, wid = tid >> 5, lane = tid & 31;

    int*   s_src = (int*)(smem + E_MISC);
    int*   s_dst = (int*)(smem + E_MISC + 512);
    float* s_pb  = (float*)(smem + E_MISC + 1024);
    float* s_b1  = (float*)(smem + E_MISC + 1280);
    float* s_b2  = (float*)(smem + E_MISC + 1792);
    float* s_ce  = (float*)(smem + E_MISC + 2048);
    float* spart = (float*)(smem + E_MISC + 2560);
    float* fstage = (float*)(smem + E_A0);  // f32 [128][68]

    load_W_seg(smem, 0,     64, 64,  72, E_WP, tid, 512);
    load_W_seg(smem, 4096,  64, 128, 136, E_W0, tid, 512);
    load_W_seg(smem, 12288, 128, 128, 136, E_W1, tid, 512);
    load_W_seg(smem, 28672, 128, 64,  72, E_W2, tid, 512);
    if (tid < 128) {
        s_ce[tid] = g_ce[tid];
        s_b1[tid] = __ldg(b1 + tid);
    } else if (tid < 192) {
        s_pb[tid - 128] = __ldg(pb + tid - 128);
    } else if (tid < 256) {
        s_b2[tid - 192] = __ldg(b2 + tid - 192);
    }
    __syncthreads();  // weights/const staged before first iteration

    int slab = wid & 7, h = wid >> 3, row0 = slab * 16;
    int g = lane >> 2, t2 = (lane & 3) * 2;
    int rA = row0 + g, rB = row0 + g + 8;
    float ue_acc = 0.0f;
    float c[8][4];

    for (int tt = blockIdx.x; tt < nTiles; tt += gridDim.x) {
        size_t base = (size_t)tt * 128;

        if (tid < 128) {
            s_src[tid] = srcI[base + tid];
            s_dst[tid] = dstI[base + tid];
        }
        // stage ef -> A0: 2048 float4s
        for (int i = tid; i < 2048; i += 512) {
            int rr = i >> 4, q = i & 15;
            float4 v = __ldg((const float4*)(ef + (base + rr) * 64) + q);
            int cc = q * 4;
            *(u32*)(smem + E_A0 + (rr * SA + cc) * 2) = pack2h(v.x, v.y);
            *(u32*)(smem + E_A0 + (rr * SA + cc + 2) * 2) = pack2h(v.z, v.w);
        }
        __syncthreads();

        // ---- phase 0: pre-edge K=64 N=64, A0 -> A1 ----
        mma_phase<64, 4>(smem, E_A0, E_WP, 72, row0, h * 32, lane, c);
#pragma unroll
        for (int n = 0; n < 4; n++)
            epi_store(smem, E_A1, rA, rB, h * 32 + n * 8 + t2, c[n], s_pb);
        __syncthreads();

        // ---- phase 1: L0 K=64 N=128 (+As[src]+Ad[dst]+ce), A1 -> A0 ----
        mma_phase<64, 8>(smem, E_A1, E_W0, 136, row0, h * 64, lane, c);
        {
            const float2* asA = (const float2*)g_As + (size_t)s_src[rA] * 64;
            const float2* adA = (const float2*)g_Ad + (size_t)s_dst[rA] * 64;
            const float2* asB = (const float2*)g_As + (size_t)s_src[rB] * 64;
            const float2* adB = (const float2*)g_Ad + (size_t)s_dst[rB] * 64;
#pragma unroll
            for (int n = 0; n < 8; n++) {
                int col = h * 64 + n * 8 + t2, ci = col >> 1;
                float2 a0 = __ldg(asA + ci), d0 = __ldg(adA + ci);
                float2 a1 = __ldg(asB + ci), d1 = __ldg(adB + ci);
                float v0 = sp(c[n][0] + a0.x + d0.x + s_ce[col]);
                float v1 = sp(c[n][1] + a0.y + d0.y + s_ce[col + 1]);
                float v2 = sp(c[n][2] + a1.x + d1.x + s_ce[col]);
                float v3 = sp(c[n][3] + a1.y + d1.y + s_ce[col + 1]);
                *(u32*)(smem + E_A0 + (rA * SA + col) * 2) = pack2h(v0, v1);
                *(u32*)(smem + E_A0 + (rB * SA + col) * 2) = pack2h(v2, v3);
            }
        }
        __syncthreads();

        // ---- phase 2: L1 K=128 N=128, A0 -> A1 ----
        mma_phase<128, 8>(smem, E_A0, E_W1, 136, row0, h * 64, lane, c);
#pragma unroll
        for (int n = 0; n < 8; n++)
            epi_store(smem, E_A1, rA, rB, h * 64 + n * 8 + t2, c[n], s_b1);
        __syncthreads();

        // ---- phase 3: L2 K=128 N=64, A1 -> global (+fstage A0) ----
        mma_phase<128, 4>(smem, E_A1, E_W2, 72, row0, h * 32, lane, c);
        {
            int dA = s_dst[rA], dB = s_dst[rB];
#pragma unroll
            for (int n = 0; n < 4; n++) {
                int col = h * 32 + n * 8 + t2;
                float v0 = sp(c[n][0] + s_b2[col]);
                float v1 = sp(c[n][1] + s_b2[col + 1]);
                float v2 = sp(c[n][2] + s_b2[col]);
                float v3 = sp(c[n][3] + s_b2[col + 1]);
                size_t gA = (base + rA) * 64 + col, gB = (base + rB) * 64 + col;
                float2 eA = __ldg((const float2*)(ef + gA));
                float2 eB = __ldg((const float2*)(ef + gB));
                float2 oA = {v0 + eA.x, v1 + eA.y};
                float2 oB = {v2 + eB.x, v3 + eB.y};
                *(float2*)(e_out + gA) = oA;
                *(float2*)(e_out + gB) = oB;
                red2(&g_ve[(size_t)dA * 64 + col], v0, v1);
                red2(&g_ve[(size_t)dB * 64 + col], v2, v3);
                fstage[rA * 68 + col] = v0;
                fstage[rA * 68 + col + 1] = v1;
                fstage[rB * 68 + col] = v2;
                fstage[rB * 68 + col + 1] = v3;
                if (n == 0 && h == 0 && t2 == 0) {
                    atomicAdd(&g_cnt[dA], 1.0f);
                    atomicAdd(&g_cnt[dB], 1.0f);
                }
            }
        }
        __syncthreads();

        // ue partial: 512 threads, 16 rows each
        {
            int col = tid & 63, q = tid >> 6;
            float s = 0.0f;
#pragma unroll
            for (int rr = q * 16; rr < q * 16 + 16; rr++) s += fstage[rr * 68 + col];
            spart[tid] = s;
        }
        __syncthreads();
        if (tid < 64) {
            float s = 0.0f;
#pragma unroll
            for (int q = 0; q < 8; q++) s += spart[q * 64 + tid];
            ue_acc += s;
        }
    }
    if (tid < 64) atomicAdd(&g_ue[tid], ue_acc);
}

// ---------------------------------------------------------------------------
// persistent node kernel: 128 nodes/iter, 512 threads, 5 syncs/iter.
// ping-pong: L0 A0->A1, L1 A1->A0, L2 A0 -> global (+fstage A1)
// ---------------------------------------------------------------------------
__global__ __launch_bounds__(512) void node_kernel(
    const float* __restrict__ nf, const float* __restrict__ b1,
    const float* __restrict__ b2, float* __restrict__ v_out, int nNodes,
    int nTiles) {
    extern __shared__ char smem[];
    int tid = threadIdx.x, wid = tid >> 5, lane = tid & 31;

    float* s_cn  = (float*)(smem + N_MISC);
    float* s_b1  = (float*)(smem + N_MISC + 512);
    float* s_b2  = (float*)(smem + N_MISC + 1024);
    float* spart = (float*)(smem + N_MISC + 1280);
    float* fstage = (float*)(smem + N_A1);

    load_W_seg(smem, 36864, 128, 128, 136, N_W0, tid, 512);
    load_W_seg(smem, 53248, 128, 128, 136, N_W1, tid, 512);
    load_W_seg(smem, 69632, 128, 64,  72, N_W2, tid, 512);
    if (tid < 128) {
        s_cn[tid] = g_cn[tid];
        s_b1[tid] = __ldg(b1 + tid);
    } else if (tid < 192) {
        s_b2[tid - 128] = (tid - 128 < 64) ? __ldg(b2 + tid - 128) : 0.0f;
    }
    __syncthreads();

    int slab = wid & 7, h = wid >> 3, row0 = slab * 16;
    int g = lane >> 2, t2 = (lane & 3) * 2;
    int rA = row0 + g, rB = row0 + g + 8;
    float uv_acc = 0.0f;
    float c[8][4];

    for (int tt = blockIdx.x; tt < nTiles; tt += gridDim.x) {
        size_t base = (size_t)tt * 128;

        // stage X = [v_pre | ve_mean] (K=128) -> A0
        {
            int rr = tid & 127, hh = tid >> 7;
            size_t gn = base + rr;
            if (gn >= (size_t)nNodes) gn = nNodes - 1;
            const float4* g4;
            float scale = 1.0f;
            if (hh < 2) {
                g4 = (const float4*)(g_v_pre + gn * 64) + hh * 8;
            } else {
                g4 = (const float4*)(g_ve + gn * 64) + (hh - 2) * 8;
                scale = 1.0f / fmaxf(g_cnt[gn], 1.0f);
            }
#pragma unroll
            for (int q = 0; q < 8; q++) {
                float4 v = __ldg(g4 + q);
                v.x *= scale; v.y *= scale; v.z *= scale; v.w *= scale;
                int cc = hh * 32 + q * 4;
                *(u32*)(smem + N_A0 + (rr * SA + cc) * 2) = pack2h(v.x, v.y);
                *(u32*)(smem + N_A0 + (rr * SA + cc + 2) * 2) = pack2h(v.z, v.w);
            }
        }
        __syncthreads();

        bool vA = (base + rA) < (size_t)nNodes;
        bool vB = (base + rB) < (size_t)nNodes;

        // ---- L0: K=128 N=128, A0 -> A1 ----
        mma_phase<128, 8>(smem, N_A0, N_W0, 136, row0, h * 64, lane, c);
#pragma unroll
        for (int n = 0; n < 8; n++)
            epi_store(smem, N_A1, rA, rB, h * 64 + n * 8 + t2, c[n], s_cn);
        __syncthreads();

        // ---- L1: K=128 N=128, A1 -> A0 ----
        mma_phase<128, 8>(smem, N_A1, N_W1, 136, row0, h * 64, lane, c);
#pragma unroll
        for (int n = 0; n < 8; n++)
            epi_store(smem, N_A0, rA, rB, h * 64 + n * 8 + t2, c[n], s_b1);
        __syncthreads();

        // ---- L2: K=128 N=64, A0 -> global (+fstage A1) ----
        mma_phase<128, 4>(smem, N_A0, N_W2, 72, row0, h * 32, lane, c);
#pragma unroll
        for (int n = 0; n < 4; n++) {
            int col = h * 32 + n * 8 + t2;
            float v0 = sp(c[n][0] + s_b2[col]);
            float v1 = sp(c[n][1] + s_b2[col + 1]);
            float v2 = sp(c[n][2] + s_b2[col]);
            float v3 = sp(c[n][3] + s_b2[col + 1]);
            if (vA) {
                size_t gA = (base + rA) * 64 + col;
                float2 eA = __ldg((const float2*)(nf + gA));
                float2 oA = {v0 + eA.x, v1 + eA.y};
                *(float2*)(v_out + gA) = oA;
            }
            if (vB) {
                size_t gB = (base + rB) * 64 + col;
                float2 eB = __ldg((const float2*)(nf + gB));
                float2 oB = {v2 + eB.x, v3 + eB.y};
                *(float2*)(v_out + gB) = oB;
            }
            fstage[rA * 68 + col] = vA ? v0 : 0.0f;
            fstage[rA * 68 + col + 1] = vA ? v1 : 0.0f;
            fstage[rB * 68 + col] = vB ? v2 : 0.0f;
            fstage[rB * 68 + col + 1] = vB ? v3 : 0.0f;
        }
        __syncthreads();

        {
            int col = tid & 63, q = tid >> 6;
            float s = 0.0f;
#pragma unroll
            for (int rr = q * 16; rr < q * 16 + 16; rr++) s += fstage[rr * 68 + col];
            spart[tid] = s;
        }
        __syncthreads();
        if (tid < 64) {
            float s = 0.0f;
#pragma unroll
            for (int q = 0; q < 8; q++) s += spart[q * 64 + tid];
            uv_acc += s;
        }
    }
    if (tid < 64) atomicAdd(&g_uv[tid], uv_acc);
}

// ---------------------------------------------------------------------------
__global__ void attr_kernel(const float* __restrict__ ga,
                            const float* __restrict__ w0,
                            const float* __restrict__ b0,
                            const float* __restrict__ w1,
                            const float* __restrict__ b1,
                            const float* __restrict__ w2,
                            const float* __restrict__ b2,
                            float* __restrict__ out, float invE, float invN) {
    __shared__ float x[192], h0[128], h1[128];
    int t = threadIdx.x;
    if (t < 64) {
        x[t]       = g_u_pre[t];
        x[64 + t]  = g_ue[t] * invE;
        x[128 + t] = g_uv[t] * invN;
    }
    __syncthreads();
    float acc = b0[t];
    for (int k = 0; k < 192; k++) acc = fmaf(x[k], w0[k * 128 + t], acc);
    h0[t] = sp(acc);
    __syncthreads();
    acc = b1[t];
    for (int k = 0; k < 128; k++) acc = fmaf(h0[k], w1[k * 128 + t], acc);
    h1[t] = sp(acc);
    __syncthreads();
    if (t < 64) {
        float a = b2[t];
        for (int k = 0; k < 128; k++) a = fmaf(h1[k], w2[k * 64 + t], a);
        out[t] = sp(a) + ga[t];
    }
}

// ---------------------------------------------------------------------------
extern "C" void kernel_launch(void* const* d_in, const int* in_sizes, int n_in,
                              void* d_out, int out_size) {
    const float* edge_feat  = (const float*)d_in[0];
    const float* node_feat  = (const float*)d_in[1];
    const float* graph_attr = (const float*)d_in[2];
    const int*   src        = (const int*)d_in[3];
    const int*   dst        = (const int*)d_in[4];
    const float* pre_edge_w = (const float*)d_in[5];
    const float* pre_edge_b = (const float*)d_in[6];
    const float* pre_node_w = (const float*)d_in[7];
    const float* pre_node_b = (const float*)d_in[8];
    const float* pre_attr_w = (const float*)d_in[9];
    const float* pre_attr_b = (const float*)d_in[10];
    const float* edge_w0 = (const float*)d_in[11];
    const float* edge_b0 = (const float*)d_in[12];
    const float* edge_w1 = (const float*)d_in[13];
    const float* edge_b1 = (const float*)d_in[14];
    const float* edge_w2 = (const float*)d_in[15];
    const float* edge_b2 = (const float*)d_in[16];
    const float* node_w0 = (const float*)d_in[17];
    const float* node_b0 = (const float*)d_in[18];
    const float* node_w1 = (const float*)d_in[19];
    const float* node_b1 = (const float*)d_in[20];
    const float* node_w2 = (const float*)d_in[21];
    const float* node_b2 = (const float*)d_in[22];
    const float* attr_w0 = (const float*)d_in[23];
    const float* attr_b0 = (const float*)d_in[24];
    const float* attr_w1 = (const float*)d_in[25];
    const float* attr_b1 = (const float*)d_in[26];
    const float* attr_w2 = (const float*)d_in[27];
    const float* attr_b2 = (const float*)d_in[28];

    float* out = (float*)d_out;
    int E = in_sizes[3];
    int N = in_sizes[1] / 64;
    int eTiles = E / 128;
    int nTiles = (N + 127) / 128;

    cudaFuncSetAttribute(edge_kernel, cudaFuncAttributeMaxDynamicSharedMemorySize,
                         E_TOTAL);
    cudaFuncSetAttribute(node_kernel, cudaFuncAttributeMaxDynamicSharedMemorySize,
                         N_TOTAL);

    zero_kernel<<<256, 256>>>(N);
    pre_attr_kernel<<<1, 64>>>(graph_attr, pre_attr_w, pre_attr_b);
    const_kernel<<<1, 128>>>(edge_w0, edge_b0, node_w0, node_b0);
    prep_w_kernel<<<64, 256>>>(pre_edge_w, edge_w0, edge_w1, edge_w2, node_w0,
                               node_w1, node_w2);
    pre_nodeA_kernel<<<N / 32, 128>>>(node_feat, pre_node_w, pre_node_b, edge_w0);
    edge_kernel<<<NUM_CTAS, 512, E_TOTAL>>>(edge_feat, src, dst, pre_edge_b,
                                            edge_b1, edge_b2, out, eTiles);
    node_kernel<<<NUM_CTAS, 512, N_TOTAL>>>(node_feat, node_b1, node_b2,
                                            out + (size_t)E * 64, N, nTiles);
    attr_kernel<<<1, 128>>>(graph_attr, attr_w0, attr_b0, attr_w1, attr_b1,
                            attr_w2, attr_b2,
                            out + (size_t)E * 64 + (size_t)N * 64,
                            1.0f / (float)E, 1.0f / (float)N);
}

// round 17
// speedup vs baseline: 1.3173x; 1.0976x over previous
#include <cuda_runtime.h>
#include <cuda_fp16.h>
#include <cstdint>
#include <cstddef>

// ---------------------------------------------------------------------------
// MegNetBlock — persistent direct mma.sync fp16 everywhere (edge/node/pre).
// N=100000, E=800000, D=64, H=128
// ---------------------------------------------------------------------------

#define NMAX 100000
typedef unsigned int u32;

// ---------------- scratch (device globals) ----------------
__device__ float  g_v_pre[NMAX * 64];
__device__ float4 g_As[NMAX * 32];
__device__ float4 g_Ad[NMAX * 32];
__device__ float  g_ve[NMAX * 64];
__device__ float  g_cnt[NMAX];
__device__ float  g_u_pre[64];
__device__ __align__(16) float g_ce[128];
__device__ __align__(16) float g_cn[128];
__device__ float  g_ue[64];
__device__ float  g_uv[64];

// fp16 weights, [k][n] row-major per segment (offsets in elems)
//  0 Wp   0     (64x64)   edge pre
//  1 W0e  4096  (64x128)  edge_w0 rows 128..191
//  2 W1e  12288 (128x128)
//  3 W2e  28672 (128x64)
//  4 W0n  36864 (128x128)
//  5 W1n  53248 (128x128)
//  6 W2n  69632 (128x64)
//  7 Wpn  77824 (64x64)   pre_node_w
//  8 W0s  81920 (64x128)  edge_w0 rows 0..63
//  9 W0d  90112 (64x128)  edge_w0 rows 64..127
__device__ __align__(16) __half g_W[98304];

// ---------------- smem layouts (byte offsets) ----------------
static constexpr int SA = 136;   // A row stride in fp16 elems

// edge kernel (512 threads, 16 warps, 128 rows/iter)
static constexpr int E_WP  = 0;        // 64x72
static constexpr int E_W0  = 9216;     // 64x136
static constexpr int E_W1  = 26624;    // 128x136
static constexpr int E_W2  = 61440;    // 128x72
static constexpr int E_A0  = 79872;    // 128x136 fp16
static constexpr int E_A1  = 114688;
static constexpr int E_MISC = 149504;  // src|dst|pb|b1|b2|ce|spart
static constexpr int E_TOTAL = 154112;

// node kernel (512 threads, 128 rows/iter)
static constexpr int N_W0  = 0;
static constexpr int N_W1  = 34816;
static constexpr int N_W2  = 69632;
static constexpr int N_A0  = 88064;
static constexpr int N_A1  = 122880;
static constexpr int N_MISC = 157696;
static constexpr int N_TOTAL = 161024;

// pre-node kernel (512 threads, 128 rows/iter)
static constexpr int P_WP  = 0;        // 64x72  = 9216
static constexpr int P_WS  = 9216;     // 64x136 = 17408
static constexpr int P_WD  = 26624;    // 17408
static constexpr int P_A0  = 44032;    // 34816
static constexpr int P_A1  = 78848;    // 34816
static constexpr int P_MISC = 113664;  // pb 256
static constexpr int P_TOTAL = 113920;

static constexpr int NUM_CTAS = 148;

// ---------------- helpers ----------------
__device__ __forceinline__ float sp(float x) {
    return fmaxf(x, 0.0f) + __logf(1.0f + __expf(-fabsf(x)));
}
__device__ __forceinline__ u32 pack2h(float a, float b) {
    __half2 h = __floats2half2_rn(a, b);
    return *(u32*)&h;
}
__device__ __forceinline__ u32 s2u(const void* p) {
    return (u32)__cvta_generic_to_shared(p);
}
__device__ __forceinline__ void ldsm_x4(u32 addr, u32* a) {
    asm volatile("ldmatrix.sync.aligned.m8n8.x4.shared.b16 {%0,%1,%2,%3},[%4];"
                 : "=r"(a[0]), "=r"(a[1]), "=r"(a[2]), "=r"(a[3]) : "r"(addr));
}
__device__ __forceinline__ void ldsm_x4t(u32 addr, u32* b) {
    asm volatile("ldmatrix.sync.aligned.m8n8.x4.trans.shared.b16 {%0,%1,%2,%3},[%4];"
                 : "=r"(b[0]), "=r"(b[1]), "=r"(b[2]), "=r"(b[3]) : "r"(addr));
}
__device__ __forceinline__ void mma16816(float* c, const u32* a, const u32* b) {
    asm volatile(
        "mma.sync.aligned.m16n8k16.row.col.f32.f16.f16.f32 "
        "{%0,%1,%2,%3},{%4,%5,%6,%7},{%8,%9},{%0,%1,%2,%3};"
        : "+f"(c[0]), "+f"(c[1]), "+f"(c[2]), "+f"(c[3])
        : "r"(a[0]), "r"(a[1]), "r"(a[2]), "r"(a[3]), "r"(b[0]), "r"(b[1]));
}
__device__ __forceinline__ void red2(float* p, float a, float b) {
    asm volatile("red.global.add.v2.f32 [%0],{%1,%2};"
                 :: "l"(p), "f"(a), "f"(b) : "memory");
}

// one warp: C[row0:16, colbase..colbase+8*NT8] = A[row0:, :K] @ W[:K, cols]
template <int K, int NT8>
__device__ __forceinline__ void mma_phase(const char* smem, int offA, int offW,
                                          int SW, int row0, int colbase, int lane,
                                          float c[][4]) {
#pragma unroll
    for (int i = 0; i < NT8; i++) {
        c[i][0] = 0.0f; c[i][1] = 0.0f; c[i][2] = 0.0f; c[i][3] = 0.0f;
    }
    const __half* A = (const __half*)(smem + offA);
    const __half* W = (const __half*)(smem + offW);
    const __half* arow = A + (row0 + (lane & 15)) * SA + ((lane >> 4) << 3);
    int q = lane >> 3, rw = lane & 7;
    const __half* brow = W + ((q & 1) * 8 + rw) * SW + colbase + (q >> 1) * 8;
#pragma unroll
    for (int k = 0; k < K; k += 16) {
        u32 a[4];
        ldsm_x4(s2u(arow + k), a);
#pragma unroll
        for (int i2 = 0; i2 < NT8 / 2; i2++) {
            u32 b[4];
            ldsm_x4t(s2u(brow + k * SW + i2 * 16), b);
            mma16816(c[2 * i2], a, b);
            mma16816(c[2 * i2 + 1], a, b + 2);
        }
    }
}

__device__ __forceinline__ void load_W_seg(char* smem, int goff, int K, int N, int SW,
                                           int off, int tid, int nthr) {
    const u32* gw = (const u32*)(g_W + goff);
    int total2 = K * N / 2;
    for (int i2 = tid; i2 < total2; i2 += nthr) {
        int k = (2 * i2) / N, n = (2 * i2) % N;
        *(u32*)(smem + off + (k * SW + n) * 2) = gw[i2];
    }
}

__device__ __forceinline__ void epi_store(char* smem, int offA, int rA, int rB,
                                          int col, const float* c,
                                          const float* bias) {
    float v0 = sp(c[0] + bias[col]);
    float v1 = sp(c[1] + bias[col + 1]);
    float v2 = sp(c[2] + bias[col]);
    float v3 = sp(c[3] + bias[col + 1]);
    *(u32*)(smem + offA + (rA * SA + col) * 2) = pack2h(v0, v1);
    *(u32*)(smem + offA + (rB * SA + col) * 2) = pack2h(v2, v3);
}

// ---------------------------------------------------------------------------
__global__ void zero_kernel(int nNodes) {
    int i0 = blockIdx.x * blockDim.x + threadIdx.x;
    int stride = gridDim.x * blockDim.x;
    float4 z = {0.0f, 0.0f, 0.0f, 0.0f};
    for (int i = i0; i < nNodes * 16; i += stride) ((float4*)g_ve)[i] = z;
    for (int i = i0; i < nNodes; i += stride) g_cnt[i] = 0.0f;
    if (i0 < 64) {
        g_ue[i0] = 0.0f;
        g_uv[i0] = 0.0f;
    }
}

__global__ void pre_attr_kernel(const float* __restrict__ ga,
                                const float* __restrict__ w,
                                const float* __restrict__ b) {
    __shared__ float sg[64];
    int t = threadIdx.x;
    sg[t] = ga[t];
    __syncthreads();
    float acc = b[t];
    for (int k = 0; k < 64; k++) acc = fmaf(sg[k], w[k * 64 + t], acc);
    g_u_pre[t] = sp(acc);
}

__global__ void const_kernel(const float* __restrict__ ew0,
                             const float* __restrict__ eb0,
                             const float* __restrict__ nw0,
                             const float* __restrict__ nb0) {
    __shared__ float su[64];
    int t = threadIdx.x;  // 128
    if (t < 64) su[t] = g_u_pre[t];
    __syncthreads();
    float a = eb0[t], c = nb0[t];
    for (int k = 0; k < 64; k++) {
        a = fmaf(su[k], ew0[(192 + k) * 128 + t], a);
        c = fmaf(su[k], nw0[(128 + k) * 128 + t], c);
    }
    g_ce[t] = a;
    g_cn[t] = c;
}

__global__ void prep_w_kernel(const float* pw, const float* ew0,
                              const float* ew1, const float* ew2,
                              const float* nw0, const float* nw1,
                              const float* nw2, const float* pnw) {
    const float* srcs[10] = {pw, ew0 + 128 * 128, ew1, ew2, nw0, nw1, nw2,
                             pnw, ew0, ew0 + 64 * 128};
    const int KN[10] = {4096, 8192, 16384, 8192, 16384, 16384, 8192,
                        4096, 8192, 8192};
    const int off[10] = {0, 4096, 12288, 28672, 36864, 53248, 69632,
                         77824, 81920, 90112};
#pragma unroll 1
    for (int s = 0; s < 10; s++) {
        const float* sc = srcs[s];
        for (int i = blockIdx.x * blockDim.x + threadIdx.x; i < KN[s];
             i += gridDim.x * blockDim.x)
            g_W[off[s] + i] = __float2half_rn(sc[i]);
    }
}

// ---------------------------------------------------------------------------
// persistent pre-node kernel: 128 nodes/iter, 512 threads, 2 syncs/iter.
// A: v_pre = sp(nf@Wpn+pb)  -> g_v_pre (fp32) + A1 (fp16)
// B: As = v_pre@W0s, Ad = v_pre@W0d  -> g_As / g_Ad (raw fp32)
// ---------------------------------------------------------------------------
__global__ __launch_bounds__(512) void pre_node_kernel(
    const float* __restrict__ nf, const float* __restrict__ pb, int nNodes,
    int nTiles) {
    extern __shared__ char smem[];
    int tid = threadIdx.x, wid = tid >> 5, lane = tid & 31;
    float* s_pb = (float*)(smem + P_MISC);

    load_W_seg(smem, 77824, 64, 64,  72, P_WP, tid, 512);
    load_W_seg(smem, 81920, 64, 128, 136, P_WS, tid, 512);
    load_W_seg(smem, 90112, 64, 128, 136, P_WD, tid, 512);
    if (tid < 64) s_pb[tid] = __ldg(pb + tid);
    __syncthreads();

    int slab = wid & 7, h = wid >> 3, row0 = slab * 16;
    int g = lane >> 2, t2 = (lane & 3) * 2;
    int rA = row0 + g, rB = row0 + g + 8;
    float c[8][4];

    for (int tt = blockIdx.x; tt < nTiles; tt += gridDim.x) {
        size_t base = (size_t)tt * 128;

        // stage nf -> A0 (clamped)
        for (int i = tid; i < 2048; i += 512) {
            int rr = i >> 4, q = i & 15;
            size_t gn = base + rr;
            if (gn >= (size_t)nNodes) gn = nNodes - 1;
            float4 v = __ldg((const float4*)(nf + gn * 64) + q);
            int cc = q * 4;
            *(u32*)(smem + P_A0 + (rr * SA + cc) * 2) = pack2h(v.x, v.y);
            *(u32*)(smem + P_A0 + (rr * SA + cc + 2) * 2) = pack2h(v.z, v.w);
        }
        __syncthreads();

        bool vA = (base + rA) < (size_t)nNodes;
        bool vB = (base + rB) < (size_t)nNodes;

        // ---- phase A: v_pre K=64 N=64, A0 -> A1 + g_v_pre ----
        mma_phase<64, 4>(smem, P_A0, P_WP, 72, row0, h * 32, lane, c);
#pragma unroll
        for (int n = 0; n < 4; n++) {
            int col = h * 32 + n * 8 + t2;
            float v0 = sp(c[n][0] + s_pb[col]);
            float v1 = sp(c[n][1] + s_pb[col + 1]);
            float v2 = sp(c[n][2] + s_pb[col]);
            float v3 = sp(c[n][3] + s_pb[col + 1]);
            *(u32*)(smem + P_A1 + (rA * SA + col) * 2) = pack2h(v0, v1);
            *(u32*)(smem + P_A1 + (rB * SA + col) * 2) = pack2h(v2, v3);
            if (vA) {
                float2 o = {v0, v1};
                *(float2*)(g_v_pre + (base + rA) * 64 + col) = o;
            }
            if (vB) {
                float2 o = {v2, v3};
                *(float2*)(g_v_pre + (base + rB) * 64 + col) = o;
            }
        }
        __syncthreads();

        // ---- phase B: As = v_pre@W0s (K=64 N=128) ----
        mma_phase<64, 8>(smem, P_A1, P_WS, 136, row0, h * 64, lane, c);
        {
            float* AsF = (float*)g_As;
#pragma unroll
            for (int n = 0; n < 8; n++) {
                int col = h * 64 + n * 8 + t2;
                if (vA) {
                    float2 o = {c[n][0], c[n][1]};
                    *(float2*)(AsF + (base + rA) * 128 + col) = o;
                }
                if (vB) {
                    float2 o = {c[n][2], c[n][3]};
                    *(float2*)(AsF + (base + rB) * 128 + col) = o;
                }
            }
        }
        // ---- Ad = v_pre@W0d ----
        mma_phase<64, 8>(smem, P_A1, P_WD, 136, row0, h * 64, lane, c);
        {
            float* AdF = (float*)g_Ad;
#pragma unroll
            for (int n = 0; n < 8; n++) {
                int col = h * 64 + n * 8 + t2;
                if (vA) {
                    float2 o = {c[n][0], c[n][1]};
                    *(float2*)(AdF + (base + rA) * 128 + col) = o;
                }
                if (vB) {
                    float2 o = {c[n][2], c[n][3]};
                    *(float2*)(AdF + (base + rB) * 128 + col) = o;
                }
            }
        }
    }
}

// ---------------------------------------------------------------------------
// persistent edge kernel: 128 edges/iter, 512 threads, 6 syncs/iter.
// ---------------------------------------------------------------------------
__global__ __launch_bounds__(512) void edge_kernel(
    const float* __restrict__ ef, const int* __restrict__ srcI,
    const int* __restrict__ dstI, const float* __restrict__ pb,
    const float* __restrict__ b1, const float* __restrict__ b2,
    float* __restrict__ e_out, int nTiles) {
    extern __shared__ char smem[];
    int tid = threadIdx.x, wid = tid >> 5, lane = tid & 31;

    int*   s_src = (int*)(smem + E_MISC);
    int*   s_dst = (int*)(smem + E_MISC + 512);
    float* s_pb  = (float*)(smem + E_MISC + 1024);
    float* s_b1  = (float*)(smem + E_MISC + 1280);
    float* s_b2  = (float*)(smem + E_MISC + 1792);
    float* s_ce  = (float*)(smem + E_MISC + 2048);
    float* spart = (float*)(smem + E_MISC + 2560);
    float* fstage = (float*)(smem + E_A0);  // f32 [128][68]

    load_W_seg(smem, 0,     64, 64,  72, E_WP, tid, 512);
    load_W_seg(smem, 4096,  64, 128, 136, E_W0, tid, 512);
    load_W_seg(smem, 12288, 128, 128, 136, E_W1, tid, 512);
    load_W_seg(smem, 28672, 128, 64,  72, E_W2, tid, 512);
    if (tid < 128) {
        s_ce[tid] = g_ce[tid];
        s_b1[tid] = __ldg(b1 + tid);
    } else if (tid < 192) {
        s_pb[tid - 128] = __ldg(pb + tid - 128);
    } else if (tid < 256) {
        s_b2[tid - 192] = __ldg(b2 + tid - 192);
    }
    __syncthreads();

    int slab = wid & 7, h = wid >> 3, row0 = slab * 16;
    int g = lane >> 2, t2 = (lane & 3) * 2;
    int rA = row0 + g, rB = row0 + g + 8;
    float ue_acc = 0.0f;
    float c[8][4];

    for (int tt = blockIdx.x; tt < nTiles; tt += gridDim.x) {
        size_t base = (size_t)tt * 128;

        if (tid < 128) {
            s_src[tid] = srcI[base + tid];
            s_dst[tid] = dstI[base + tid];
        }
        for (int i = tid; i < 2048; i += 512) {
            int rr = i >> 4, q = i & 15;
            float4 v = __ldg((const float4*)(ef + (base + rr) * 64) + q);
            int cc = q * 4;
            *(u32*)(smem + E_A0 + (rr * SA + cc) * 2) = pack2h(v.x, v.y);
            *(u32*)(smem + E_A0 + (rr * SA + cc + 2) * 2) = pack2h(v.z, v.w);
        }
        __syncthreads();

        // ---- phase 0: pre-edge K=64 N=64, A0 -> A1 ----
        mma_phase<64, 4>(smem, E_A0, E_WP, 72, row0, h * 32, lane, c);
#pragma unroll
        for (int n = 0; n < 4; n++)
            epi_store(smem, E_A1, rA, rB, h * 32 + n * 8 + t2, c[n], s_pb);
        __syncthreads();

        // ---- phase 1: L0 K=64 N=128 (+As[src]+Ad[dst]+ce), A1 -> A0 ----
        mma_phase<64, 8>(smem, E_A1, E_W0, 136, row0, h * 64, lane, c);
        {
            const float2* asA = (const float2*)g_As + (size_t)s_src[rA] * 64;
            const float2* adA = (const float2*)g_Ad + (size_t)s_dst[rA] * 64;
            const float2* asB = (const float2*)g_As + (size_t)s_src[rB] * 64;
            const float2* adB = (const float2*)g_Ad + (size_t)s_dst[rB] * 64;
#pragma unroll
            for (int n = 0; n < 8; n++) {
                int col = h * 64 + n * 8 + t2, ci = col >> 1;
                float2 a0 = __ldg(asA + ci), d0 = __ldg(adA + ci);
                float2 a1 = __ldg(asB + ci), d1 = __ldg(adB + ci);
                float v0 = sp(c[n][0] + a0.x + d0.x + s_ce[col]);
                float v1 = sp(c[n][1] + a0.y + d0.y + s_ce[col + 1]);
                float v2 = sp(c[n][2] + a1.x + d1.x + s_ce[col]);
                float v3 = sp(c[n][3] + a1.y + d1.y + s_ce[col + 1]);
                *(u32*)(smem + E_A0 + (rA * SA + col) * 2) = pack2h(v0, v1);
                *(u32*)(smem + E_A0 + (rB * SA + col) * 2) = pack2h(v2, v3);
            }
        }
        __syncthreads();

        // ---- phase 2: L1 K=128 N=128, A0 -> A1 ----
        mma_phase<128, 8>(smem, E_A0, E_W1, 136, row0, h * 64, lane, c);
#pragma unroll
        for (int n = 0; n < 8; n++)
            epi_store(smem, E_A1, rA, rB, h * 64 + n * 8 + t2, c[n], s_b1);
        __syncthreads();

        // ---- phase 3: L2 K=128 N=64, A1 -> global (+fstage A0) ----
        mma_phase<128, 4>(smem, E_A1, E_W2, 72, row0, h * 32, lane, c);
        {
            int dA = s_dst[rA], dB = s_dst[rB];
#pragma unroll
            for (int n = 0; n < 4; n++) {
                int col = h * 32 + n * 8 + t2;
                float v0 = sp(c[n][0] + s_b2[col]);
                float v1 = sp(c[n][1] + s_b2[col + 1]);
                float v2 = sp(c[n][2] + s_b2[col]);
                float v3 = sp(c[n][3] + s_b2[col + 1]);
                size_t gA = (base + rA) * 64 + col, gB = (base + rB) * 64 + col;
                float2 eA = __ldg((const float2*)(ef + gA));
                float2 eB = __ldg((const float2*)(ef + gB));
                float2 oA = {v0 + eA.x, v1 + eA.y};
                float2 oB = {v2 + eB.x, v3 + eB.y};
                *(float2*)(e_out + gA) = oA;
                *(float2*)(e_out + gB) = oB;
                red2(&g_ve[(size_t)dA * 64 + col], v0, v1);
                red2(&g_ve[(size_t)dB * 64 + col], v2, v3);
                fstage[rA * 68 + col] = v0;
                fstage[rA * 68 + col + 1] = v1;
                fstage[rB * 68 + col] = v2;
                fstage[rB * 68 + col + 1] = v3;
                if (n == 0 && h == 0 && t2 == 0) {
                    atomicAdd(&g_cnt[dA], 1.0f);
                    atomicAdd(&g_cnt[dB], 1.0f);
                }
            }
        }
        __syncthreads();

        {
            int col = tid & 63, q = tid >> 6;
            float s = 0.0f;
#pragma unroll
            for (int rr = q * 16; rr < q * 16 + 16; rr++) s += fstage[rr * 68 + col];
            spart[tid] = s;
        }
        __syncthreads();
        if (tid < 64) {
            float s = 0.0f;
#pragma unroll
            for (int q = 0; q < 8; q++) s += spart[q * 64 + tid];
            ue_acc += s;
        }
    }
    if (tid < 64) atomicAdd(&g_ue[tid], ue_acc);
}

// ---------------------------------------------------------------------------
// persistent node kernel: 128 nodes/iter, 512 threads, 5 syncs/iter.
// ---------------------------------------------------------------------------
__global__ __launch_bounds__(512) void node_kernel(
    const float* __restrict__ nf, const float* __restrict__ b1,
    const float* __restrict__ b2, float* __restrict__ v_out, int nNodes,
    int nTiles) {
    extern __shared__ char smem[];
    int tid = threadIdx.x, wid = tid >> 5, lane = tid & 31;

    float* s_cn  = (float*)(smem + N_MISC);
    float* s_b1  = (float*)(smem + N_MISC + 512);
    float* s_b2  = (float*)(smem + N_MISC + 1024);
    float* spart = (float*)(smem + N_MISC + 1280);
    float* fstage = (float*)(smem + N_A1);

    load_W_seg(smem, 36864, 128, 128, 136, N_W0, tid, 512);
    load_W_seg(smem, 53248, 128, 128, 136, N_W1, tid, 512);
    load_W_seg(smem, 69632, 128, 64,  72, N_W2, tid, 512);
    if (tid < 128) {
        s_cn[tid] = g_cn[tid];
        s_b1[tid] = __ldg(b1 + tid);
    } else if (tid < 192) {
        s_b2[tid - 128] = (tid - 128 < 64) ? __ldg(b2 + tid - 128) : 0.0f;
    }
    __syncthreads();

    int slab = wid & 7, h = wid >> 3, row0 = slab * 16;
    int g = lane >> 2, t2 = (lane & 3) * 2;
    int rA = row0 + g, rB = row0 + g + 8;
    float uv_acc = 0.0f;
    float c[8][4];

    for (int tt = blockIdx.x; tt < nTiles; tt += gridDim.x) {
        size_t base = (size_t)tt * 128;

        {
            int rr = tid & 127, hh = tid >> 7;
            size_t gn = base + rr;
            if (gn >= (size_t)nNodes) gn = nNodes - 1;
            const float4* g4;
            float scale = 1.0f;
            if (hh < 2) {
                g4 = (const float4*)(g_v_pre + gn * 64) + hh * 8;
            } else {
                g4 = (const float4*)(g_ve + gn * 64) + (hh - 2) * 8;
                scale = 1.0f / fmaxf(g_cnt[gn], 1.0f);
            }
#pragma unroll
            for (int q = 0; q < 8; q++) {
                float4 v = __ldg(g4 + q);
                v.x *= scale; v.y *= scale; v.z *= scale; v.w *= scale;
                int cc = hh * 32 + q * 4;
                *(u32*)(smem + N_A0 + (rr * SA + cc) * 2) = pack2h(v.x, v.y);
                *(u32*)(smem + N_A0 + (rr * SA + cc + 2) * 2) = pack2h(v.z, v.w);
            }
        }
        __syncthreads();

        bool vA = (base + rA) < (size_t)nNodes;
        bool vB = (base + rB) < (size_t)nNodes;

        // ---- L0: K=128 N=128, A0 -> A1 ----
        mma_phase<128, 8>(smem, N_A0, N_W0, 136, row0, h * 64, lane, c);
#pragma unroll
        for (int n = 0; n < 8; n++)
            epi_store(smem, N_A1, rA, rB, h * 64 + n * 8 + t2, c[n], s_cn);
        __syncthreads();

        // ---- L1: K=128 N=128, A1 -> A0 ----
        mma_phase<128, 8>(smem, N_A1, N_W1, 136, row0, h * 64, lane, c);
#pragma unroll
        for (int n = 0; n < 8; n++)
            epi_store(smem, N_A0, rA, rB, h * 64 + n * 8 + t2, c[n], s_b1);
        __syncthreads();

        // ---- L2: K=128 N=64, A0 -> global (+fstage A1) ----
        mma_phase<128, 4>(smem, N_A0, N_W2, 72, row0, h * 32, lane, c);
#pragma unroll
        for (int n = 0; n < 4; n++) {
            int col = h * 32 + n * 8 + t2;
            float v0 = sp(c[n][0] + s_b2[col]);
            float v1 = sp(c[n][1] + s_b2[col + 1]);
            float v2 = sp(c[n][2] + s_b2[col]);
            float v3 = sp(c[n][3] + s_b2[col + 1]);
            if (vA) {
                size_t gA = (base + rA) * 64 + col;
                float2 eA = __ldg((const float2*)(nf + gA));
                float2 oA = {v0 + eA.x, v1 + eA.y};
                *(float2*)(v_out + gA) = oA;
            }
            if (vB) {
                size_t gB = (base + rB) * 64 + col;
                float2 eB = __ldg((const float2*)(nf + gB));
                float2 oB = {v2 + eB.x, v3 + eB.y};
                *(float2*)(v_out + gB) = oB;
            }
            fstage[rA * 68 + col] = vA ? v0 : 0.0f;
            fstage[rA * 68 + col + 1] = vA ? v1 : 0.0f;
            fstage[rB * 68 + col] = vB ? v2 : 0.0f;
            fstage[rB * 68 + col + 1] = vB ? v3 : 0.0f;
        }
        __syncthreads();

        {
            int col = tid & 63, q = tid >> 6;
            float s = 0.0f;
#pragma unroll
            for (int rr = q * 16; rr < q * 16 + 16; rr++) s += fstage[rr * 68 + col];
            spart[tid] = s;
        }
        __syncthreads();
        if (tid < 64) {
            float s = 0.0f;
#pragma unroll
            for (int q = 0; q < 8; q++) s += spart[q * 64 + tid];
            uv_acc += s;
        }
    }
    if (tid < 64) atomicAdd(&g_uv[tid], uv_acc);
}

// ---------------------------------------------------------------------------
__global__ void attr_kernel(const float* __restrict__ ga,
                            const float* __restrict__ w0,
                            const float* __restrict__ b0,
                            const float* __restrict__ w1,
                            const float* __restrict__ b1,
                            const float* __restrict__ w2,
                            const float* __restrict__ b2,
                            float* __restrict__ out, float invE, float invN) {
    __shared__ float x[192], h0[128], h1[128];
    int t = threadIdx.x;
    if (t < 64) {
        x[t]       = g_u_pre[t];
        x[64 + t]  = g_ue[t] * invE;
        x[128 + t] = g_uv[t] * invN;
    }
    __syncthreads();
    float acc = b0[t];
    for (int k = 0; k < 192; k++) acc = fmaf(x[k], w0[k * 128 + t], acc);
    h0[t] = sp(acc);
    __syncthreads();
    acc = b1[t];
    for (int k = 0; k < 128; k++) acc = fmaf(h0[k], w1[k * 128 + t], acc);
    h1[t] = sp(acc);
    __syncthreads();
    if (t < 64) {
        float a = b2[t];
        for (int k = 0; k < 128; k++) a = fmaf(h1[k], w2[k * 64 + t], a);
        out[t] = sp(a) + ga[t];
    }
}

// ---------------------------------------------------------------------------
extern "C" void kernel_launch(void* const* d_in, const int* in_sizes, int n_in,
                              void* d_out, int out_size) {
    const float* edge_feat  = (const float*)d_in[0];
    const float* node_feat  = (const float*)d_in[1];
    const float* graph_attr = (const float*)d_in[2];
    const int*   src        = (const int*)d_in[3];
    const int*   dst        = (const int*)d_in[4];
    const float* pre_edge_w = (const float*)d_in[5];
    const float* pre_edge_b = (const float*)d_in[6];
    const float* pre_node_w = (const float*)d_in[7];
    const float* pre_node_b = (const float*)d_in[8];
    const float* pre_attr_w = (const float*)d_in[9];
    const float* pre_attr_b = (const float*)d_in[10];
    const float* edge_w0 = (const float*)d_in[11];
    const float* edge_b0 = (const float*)d_in[12];
    const float* edge_w1 = (const float*)d_in[13];
    const float* edge_b1 = (const float*)d_in[14];
    const float* edge_w2 = (const float*)d_in[15];
    const float* edge_b2 = (const float*)d_in[16];
    const float* node_w0 = (const float*)d_in[17];
    const float* node_b0 = (const float*)d_in[18];
    const float* node_w1 = (const float*)d_in[19];
    const float* node_b1 = (const float*)d_in[20];
    const float* node_w2 = (const float*)d_in[21];
    const float* node_b2 = (const float*)d_in[22];
    const float* attr_w0 = (const float*)d_in[23];
    const float* attr_b0 = (const float*)d_in[24];
    const float* attr_w1 = (const float*)d_in[25];
    const float* attr_b1 = (const float*)d_in[26];
    const float* attr_w2 = (const float*)d_in[27];
    const float* attr_b2 = (const float*)d_in[28];

    float* out = (float*)d_out;
    int E = in_sizes[3];
    int N = in_sizes[1] / 64;
    int eTiles = E / 128;
    int nTiles = (N + 127) / 128;

    cudaFuncSetAttribute(edge_kernel, cudaFuncAttributeMaxDynamicSharedMemorySize,
                         E_TOTAL);
    cudaFuncSetAttribute(node_kernel, cudaFuncAttributeMaxDynamicSharedMemorySize,
                         N_TOTAL);
    cudaFuncSetAttribute(pre_node_kernel,
                         cudaFuncAttributeMaxDynamicSharedMemorySize, P_TOTAL);

    zero_kernel<<<512, 256>>>(N);
    pre_attr_kernel<<<1, 64>>>(graph_attr, pre_attr_w, pre_attr_b);
    const_kernel<<<1, 128>>>(edge_w0, edge_b0, node_w0, node_b0);
    prep_w_kernel<<<64, 256>>>(pre_edge_w, edge_w0, edge_w1, edge_w2, node_w0,
                               node_w1, node_w2, pre_node_w);
    pre_node_kernel<<<NUM_CTAS, 512, P_TOTAL>>>(node_feat, pre_node_b, N, nTiles);
    edge_kernel<<<NUM_CTAS, 512, E_TOTAL>>>(edge_feat, src, dst, pre_edge_b,
                                            edge_b1, edge_b2, out, eTiles);
    node_kernel<<<NUM_CTAS, 512, N_TOTAL>>>(node_feat, node_b1, node_b2,
                                            out + (size_t)E * 64, N, nTiles);
    attr_kernel<<<1, 128>>>(graph_attr, attr_w0, attr_b0, attr_w1, attr_b1,
                            attr_w2, attr_b2,
                            out + (size_t)E * 64 + (size_t)N * 64,
                            1.0f / (float)E, 1.0f / (float)N);
}